// round 10
// baseline (speedup 1.0000x reference)
#include <cuda_runtime.h>
#include <stdint.h>
#include <math.h>

// ---------------- problem constants ----------------
#define Bn   4
#define Cn   512
#define Hn   768
#define NHn  12
#define NEn  20
#define MMn  23
#define Pn   380
#define BPn  1520
#define QSn  128
#define EMBn 768
#define NBn  12
#define BLKn 64
#define NCLSn 97
#define POSn 128

static __device__ __constant__ float kNEG = -10000.0f;
#define SCALE_EMB 0.03608439182435161f   // 1/sqrt(768)

// ---------------- scratch ----------------
#define OFF_ENT_EMB 0UL
#define OFF_ENT_ATT (OFF_ENT_EMB + 1840UL*768)
#define OFF_ENT_Q   (OFF_ENT_ATT + 960UL*512)
#define OFF_HT_ATT  (OFF_ENT_Q   + 1840UL*128)
#define OFF_RS      (OFF_HT_ATT  + 1520UL*512)
#define OFF_HTQ     (OFF_RS      + 1520UL*768)
#define OFF_HS_ATT  (OFF_HTQ     + 1520UL*128)
#define OFF_TS_ATT  (OFF_HS_ATT  + 1520UL*768)
#define OFF_CAT_H   (OFF_TS_ATT  + 1520UL*768)
#define OFF_CAT_T   (OFF_CAT_H   + 1520UL*1536)
#define OFF_HS      (OFF_CAT_T   + 1520UL*1536)
#define OFF_TS      (OFF_HS      + 1520UL*768)
#define OFF_PAIRG   (OFF_TS      + 1520UL*768)
#define OFF_CATPP   (OFF_PAIRG   + 1520UL*768)
#define OFF_PAIR1   (OFF_CATPP   + 1520UL*1024)
#define OFF_QB      (OFF_PAIR1   + 1520UL*768)
#define OFF_KB      (OFF_QB      + 1520UL*768)
#define OFF_VB      (OFF_KB      + 1520UL*768)
#define OFF_SC      (OFF_VB      + 1520UL*768)
#define OFF_ATTO    (OFF_SC      + 4UL*380*380)
#define OFF_CATF    (OFF_ATTO    + 1520UL*768)
#define OFF_H1      (OFF_CATF    + 1520UL*2304)
#define OFF_WCAT    (OFF_H1      + 1520UL*768)
#define OFF_WQKV    (OFF_WCAT    + 2UL*1536*768)
#define OFF_WB      (OFF_WQKV    + 3UL*768*768)
#define SCRATCH_TOTAL (OFF_WB    + 2UL*768)

__device__ float g_scratch[SCRATCH_TOTAL];

// ---------------- helpers ----------------
__device__ __forceinline__ uint32_t f2tf32(float x) {
    uint32_t r; asm("cvt.rna.tf32.f32 %0, %1;" : "=r"(r) : "f"(x)); return r;
}
__device__ __forceinline__ void mma_tf32(float* c, const uint32_t* a, const uint32_t* b) {
    asm volatile("mma.sync.aligned.m16n8k8.row.col.f32.tf32.tf32.f32 "
        "{%0,%1,%2,%3}, {%4,%5,%6,%7}, {%8,%9}, {%0,%1,%2,%3};"
        : "+f"(c[0]), "+f"(c[1]), "+f"(c[2]), "+f"(c[3])
        : "r"(a[0]), "r"(a[1]), "r"(a[2]), "r"(a[3]), "r"(b[0]), "r"(b[1]));
}
__device__ __forceinline__ void cp16(void* s, const void* g, int sz) {
    uint32_t sa = (uint32_t)__cvta_generic_to_shared(s);
    asm volatile("cp.async.cg.shared.global [%0], [%1], 16, %2;" :: "r"(sa), "l"(g), "r"(sz));
}
__device__ __forceinline__ void cp4(void* s, const void* g, int sz) {
    uint32_t sa = (uint32_t)__cvta_generic_to_shared(s);
    asm volatile("cp.async.ca.shared.global [%0], [%1], 4, %2;" :: "r"(sa), "l"(g), "r"(sz));
}
__device__ __forceinline__ void cp_commit() { asm volatile("cp.async.commit_group;"); }
template<int Ng> __device__ __forceinline__ void cp_wait() {
    asm volatile("cp.async.wait_group %0;" :: "n"(Ng));
}
// ---- bulk-copy + mbarrier (Blackwell path) ----
__device__ __forceinline__ void mbar_init(uint32_t a, uint32_t cnt) {
    asm volatile("mbarrier.init.shared.b64 [%0], %1;" :: "r"(a), "r"(cnt) : "memory");
}
__device__ __forceinline__ void mbar_expect(uint32_t a, uint32_t tx) {
    asm volatile("mbarrier.arrive.expect_tx.shared.b64 _, [%0], %1;" :: "r"(a), "r"(tx) : "memory");
}
__device__ __forceinline__ void mbar_wait(uint32_t a, uint32_t ph) {
    asm volatile("{\n\t.reg .pred p;\nWAITLP%=:\n\t"
        "mbarrier.try_wait.parity.acquire.cta.shared::cta.b64 p, [%0], %1, 0x989680;\n\t"
        "@!p bra WAITLP%=;\n\t}" :: "r"(a), "r"(ph) : "memory");
}
__device__ __forceinline__ void bulk_cp(uint32_t smem_addr, const void* g, uint32_t bytes, uint32_t mbar) {
    asm volatile("cp.async.bulk.shared::cta.global.mbarrier::complete_tx::bytes [%0], [%1], %2, [%3];"
        :: "r"(smem_addr), "l"(g), "r"(bytes), "r"(mbar) : "memory");
}

// ---------------- tf32 GEMM: 64x64xBK32, 256 thr (8 warps of 16x32), 3-stage cp.async ----------------
#define GT_BM 64
#define GT_BN 64
#define GT_BK 32
#define GT_SMEM (3 * 2304 * 2 * 4)

template<bool TRANSB, bool BIAS, bool TANH>
__global__ __launch_bounds__(256, 2)
void gemm_tc(const float* __restrict__ A, const float* __restrict__ Bm,
             const float* __restrict__ bias, float* __restrict__ C,
             int M, int N, int K, int lda, int ldb, int ldc,
             long sA, long sB, long sC, float alpha, long sBias)
{
    extern __shared__ float sm[];
    float* As = sm;                     // [3][64][36]
    float* Bs = sm + 3 * 2304;          // [3][32][72] (!T) or [3][64][36] (T)
    const int tid = threadIdx.x;
    const int wid = tid >> 5, lane = tid & 31;
    const int gid = lane >> 2, tig = lane & 3;
    const int m0 = blockIdx.y * GT_BM, n0 = blockIdx.x * GT_BN;
    A  += (long)blockIdx.z * sA;
    Bm += (long)blockIdx.z * sB;
    C  += (long)blockIdx.z * sC;
    if (BIAS) bias += (long)blockIdx.z * sBias;
    const int wm0 = (wid & 3) * 16, wn0 = (wid >> 2) * 32;
    float acc[4][4] = {};

    const int ar = tid >> 2, akc = (tid & 3) * 8;     // A / T-B loads: 64 rows x 8 floats
    const int bkr = tid >> 3, bnc = (tid & 7) * 8;    // B(!T): 32 rows x 8 floats
    const bool a_ok = (m0 + ar) < M;
    const bool b4 = (!TRANSB) && (((ldb & 3) != 0) || ((N & 3) != 0));
    const int nk = (K + GT_BK - 1) / GT_BK;

    auto issueA = [&](int kt, int st) {
        float* dst = As + st * 2304 + ar * 36 + akc;
        const float* src = A + (long)(m0 + ar) * lda + kt * GT_BK + akc;
        #pragma unroll
        for (int q = 0; q < 2; ++q) {
            int sz = (a_ok && (kt * GT_BK + akc + 4 * q) < K) ? 16 : 0;
            cp16(dst + 4 * q, src + 4 * q, sz);
        }
    };
    auto issueB = [&](int kt, int st) {
        if (!TRANSB) {
            float* dst = Bs + st * 2304 + bkr * 72 + bnc;
            const float* src = Bm + (long)(kt * GT_BK + bkr) * ldb + n0 + bnc;
            const bool kok = (kt * GT_BK + bkr) < K;
            if (!b4) {
                #pragma unroll
                for (int q = 0; q < 2; ++q) {
                    int sz = (kok && (n0 + bnc + 4 * q) < N) ? 16 : 0;
                    cp16(dst + 4 * q, src + 4 * q, sz);
                }
            } else {
                #pragma unroll
                for (int e = 0; e < 8; ++e) {
                    int sz = (kok && (n0 + bnc + e) < N) ? 4 : 0;
                    cp4(dst + e, src + e, sz);
                }
            }
        } else {
            float* dst = Bs + st * 2304 + ar * 36 + akc;
            const float* src = Bm + (long)(n0 + ar) * ldb + kt * GT_BK + akc;
            const bool nok = (n0 + ar) < N;
            #pragma unroll
            for (int q = 0; q < 2; ++q) {
                int sz = (nok && (kt * GT_BK + akc + 4 * q) < K) ? 16 : 0;
                cp16(dst + 4 * q, src + 4 * q, sz);
            }
        }
    };

    issueA(0, 0); issueB(0, 0); cp_commit();
    if (nk > 1) { issueA(1, 1); issueB(1, 1); }
    cp_commit();

    int st = 0;
    for (int kt = 0; kt < nk; ++kt) {
        cp_wait<1>();
        __syncthreads();
        const int ktn = kt + 2;
        if (ktn < nk) {
            const int stn = (st + 2 >= 3) ? st - 1 : st + 2;
            issueA(ktn, stn); issueB(ktn, stn);
        }
        cp_commit();
        const float* Ac = As + st * 2304;
        const float* Bc = Bs + st * 2304;
        #pragma unroll
        for (int kk = 0; kk < GT_BK; kk += 8) {
            uint32_t af[4], bf[4][2];
            af[0] = f2tf32(Ac[(wm0 + gid) * 36 + kk + tig]);
            af[1] = f2tf32(Ac[(wm0 + 8 + gid) * 36 + kk + tig]);
            af[2] = f2tf32(Ac[(wm0 + gid) * 36 + kk + tig + 4]);
            af[3] = f2tf32(Ac[(wm0 + 8 + gid) * 36 + kk + tig + 4]);
            #pragma unroll
            for (int nf = 0; nf < 4; ++nf) {
                const int c = wn0 + nf * 8 + gid;
                if (!TRANSB) {
                    bf[nf][0] = f2tf32(Bc[(kk + tig) * 72 + c]);
                    bf[nf][1] = f2tf32(Bc[(kk + tig + 4) * 72 + c]);
                } else {
                    bf[nf][0] = f2tf32(Bc[c * 36 + kk + tig]);
                    bf[nf][1] = f2tf32(Bc[c * 36 + kk + tig + 4]);
                }
            }
            #pragma unroll
            for (int nf = 0; nf < 4; ++nf)
                mma_tf32(acc[nf], af, bf[nf]);
        }
        st = (st + 1 >= 3) ? 0 : st + 1;
    }
    // ---- epilogue ----
    #pragma unroll
    for (int nf = 0; nf < 4; ++nf) {
        const int r = m0 + wm0 + gid;
        const int c = n0 + wn0 + nf * 8 + tig * 2;
        #pragma unroll
        for (int half = 0; half < 2; ++half) {
            const int rr = r + half * 8;
            if (rr >= M) continue;
            #pragma unroll
            for (int j = 0; j < 2; ++j) {
                const int cc = c + j;
                if (cc >= N) continue;
                float v = acc[nf][half * 2 + j] * alpha;
                if (BIAS) v += bias[cc];
                if (TANH) v = tanhf(v);
                C[(long)rr * ldc + cc] = v;
            }
        }
    }
}

// ---------------- bilinear: 512 thr, M-tile 128, W streamed via cp.async.bulk + mbarrier ----------------
// C[m,n] = sum_{nb,i,j} Hs[m,nb*64+i]*Ts[m,nb*64+j]*W[(nb*4096+i*64+j), n] + bias[n]
// smem: bh[128][68], bt[128][68], Ws[4][64][72], mbar[4]
#define BL_WS_OFF   (2 * 128 * 68)
#define BL_MBAR_OFF (BL_WS_OFF + 4 * 64 * 72)
#define BL_SMEM     ((BL_MBAR_OFF + 16) * 4)
__global__ __launch_bounds__(512)
void bilinear_tc(const float* __restrict__ Hs, const float* __restrict__ Ts,
                 const float* __restrict__ W, const float* __restrict__ bias,
                 float* __restrict__ C, int M)
{
    extern __shared__ float sm[];
    float* bh = sm;                      // [128][68]
    float* bt = sm + 128 * 68;           // [128][68]
    float* Ws = sm + BL_WS_OFF;          // [4][64][72]
    const uint32_t ws_u32   = (uint32_t)__cvta_generic_to_shared(Ws);
    const uint32_t mbar_u32 = (uint32_t)__cvta_generic_to_shared(sm + BL_MBAR_OFF);
    const int tid = threadIdx.x;
    const int wid = tid >> 5, lane = tid & 31;
    const int gid = lane >> 2, tig = lane & 3;
    const int m0 = blockIdx.y * 128, n0 = blockIdx.x * 64;
    const int wm0 = (wid & 3) * 32, wn0 = (wid >> 2) * 16;   // 16 warps: 4m x 4n
    float acc[2][2][4] = {};
    const int lr = tid >> 2, lc = (tid & 3) * 16;            // HT loads: 128 rows
    const bool lok = (m0 + lr) < M;
    uint32_t btf[2][8][4];
    const int NT = NBn * 64;

#define LOADHT(nb_) { \
    const float* hp = Hs + (long)(m0 + lr) * 768 + (nb_) * 64 + lc; \
    const float* tp = Ts + (long)(m0 + lr) * 768 + (nb_) * 64 + lc; \
    _Pragma("unroll") for (int q_ = 0; q_ < 4; ++q_) { \
        float4 hv = lok ? *(const float4*)(hp + 4 * q_) : make_float4(0, 0, 0, 0); \
        float4 tv = lok ? *(const float4*)(tp + 4 * q_) : make_float4(0, 0, 0, 0); \
        *(float4*)&bh[lr * 68 + lc + 4 * q_] = hv; \
        *(float4*)&bt[lr * 68 + lc + 4 * q_] = tv; } }

// 64 bulk copies (one 256B row each, by threads 0..63) + expect_tx by thread 0
#define ISSUEW(t_, st_) { \
    if (tid == 0) mbar_expect(mbar_u32 + (st_) * 8, 16384u); \
    if (tid < 64) { \
        bulk_cp(ws_u32 + (st_) * 18432 + tid * 288, \
                W + ((long)(t_) * 64 + tid) * 768 + n0, 256u, \
                mbar_u32 + (st_) * 8); } }

#define CACHEBT() { \
    _Pragma("unroll") for (int mf_ = 0; mf_ < 2; ++mf_) { const int r0_ = wm0 + mf_ * 16; \
        _Pragma("unroll") for (int j0_ = 0; j0_ < 8; ++j0_) { \
            btf[mf_][j0_][0] = f2tf32(bt[(r0_ + gid) * 68 + j0_ * 8 + tig]); \
            btf[mf_][j0_][1] = f2tf32(bt[(r0_ + 8 + gid) * 68 + j0_ * 8 + tig]); \
            btf[mf_][j0_][2] = f2tf32(bt[(r0_ + gid) * 68 + j0_ * 8 + tig + 4]); \
            btf[mf_][j0_][3] = f2tf32(bt[(r0_ + 8 + gid) * 68 + j0_ * 8 + tig + 4]); } } }

    if (tid == 0) {
        mbar_init(mbar_u32 + 0, 1);
        mbar_init(mbar_u32 + 8, 1);
        mbar_init(mbar_u32 + 16, 1);
        mbar_init(mbar_u32 + 24, 1);
    }
    LOADHT(0);
    __syncthreads();               // barriers initialized + bh/bt visible
    ISSUEW(0, 0);
    ISSUEW(1, 1);
    ISSUEW(2, 2);
    CACHEBT();

    for (int t = 0; t < NT; ++t) {
        const int st = t & 3;
        mbar_wait(mbar_u32 + st * 8, (t >> 2) & 1);
        __syncthreads();           // everyone past step t-1 compute; stage (t+3)&3 free
        if (t + 3 < NT) { ISSUEW(t + 3, (t + 3) & 3); }
        const float* Wc = Ws + st * 4608;
        const int i = t & 63;
        float D[2][2][4] = {};
        #pragma unroll
        for (int j0 = 0; j0 < 8; ++j0) {
            uint32_t bfp[2][2];
            #pragma unroll
            for (int nf = 0; nf < 2; ++nf) {
                bfp[nf][0] = f2tf32(Wc[(j0 * 8 + tig) * 72 + wn0 + nf * 8 + gid]);
                bfp[nf][1] = f2tf32(Wc[(j0 * 8 + tig + 4) * 72 + wn0 + nf * 8 + gid]);
            }
            #pragma unroll
            for (int mf = 0; mf < 2; ++mf)
                #pragma unroll
                for (int nf = 0; nf < 2; ++nf)
                    mma_tf32(D[mf][nf], btf[mf][j0], bfp[nf]);
        }
        #pragma unroll
        for (int mf = 0; mf < 2; ++mf) {
            const float b0 = bh[(wm0 + mf * 16 + gid) * 68 + i];
            const float b1 = bh[(wm0 + mf * 16 + 8 + gid) * 68 + i];
            #pragma unroll
            for (int nf = 0; nf < 2; ++nf) {
                acc[mf][nf][0] = fmaf(b0, D[mf][nf][0], acc[mf][nf][0]);
                acc[mf][nf][1] = fmaf(b0, D[mf][nf][1], acc[mf][nf][1]);
                acc[mf][nf][2] = fmaf(b1, D[mf][nf][2], acc[mf][nf][2]);
                acc[mf][nf][3] = fmaf(b1, D[mf][nf][3], acc[mf][nf][3]);
            }
        }
        if ((t & 63) == 63 && t + 1 < NT) {
            __syncthreads();
            LOADHT((t + 1) >> 6);
            __syncthreads();
            CACHEBT();
        }
    }
#undef LOADHT
#undef ISSUEW
#undef CACHEBT
    #pragma unroll
    for (int mf = 0; mf < 2; ++mf) {
        #pragma unroll
        for (int nf = 0; nf < 2; ++nf) {
            const int r = m0 + wm0 + mf * 16 + gid;
            const int c = n0 + wn0 + nf * 8 + tig * 2;
            if (r < M) {
                C[(long)r * 768 + c]     = acc[mf][nf][0] + bias[c];
                C[(long)r * 768 + c + 1] = acc[mf][nf][1] + bias[c + 1];
            }
            if (r + 8 < M) {
                C[(long)(r + 8) * 768 + c]     = acc[mf][nf][2] + bias[c];
                C[(long)(r + 8) * 768 + c + 1] = acc[mf][nf][3] + bias[c + 1];
            }
        }
    }
}

// ---------------- small fused kernels ----------------
__global__ void ent_emb_k(const float* __restrict__ seq, const int* __restrict__ midx,
                          const float* __restrict__ mmask, float* __restrict__ ent_emb)
{
    const int blk = blockIdx.x;
    const int b = blk / (MMn * NEn);
    const int idx = midx[blk];
    const float mask = mmask[blk];
    const float* src = seq + ((long)b * Cn + idx) * Hn;
    float* dst = ent_emb + (long)blk * Hn;
    for (int h = threadIdx.x; h < Hn; h += 256) dst[h] = mask * src[h];
}

__global__ void ent_att_k(const float* __restrict__ att, const int* __restrict__ midx,
                          const float* __restrict__ mmask, float* __restrict__ ent_att)
{
    const int blk = blockIdx.x;
    const int nh = blk % NHn;
    const int e  = (blk / NHn) % NEn;
    const int b  = blk / (NHn * NEn);
    const int c  = threadIdx.x;
    const int* mi = midx + (b * NEn + e) * MMn;
    const float* mk = mmask + (b * NEn + e) * MMn;
    float cnt = 0.f, s = 0.f;
    for (int m = 0; m < MMn; ++m) {
        const float w = mk[m];
        cnt += w;
        s += w * att[(((long)b * NHn + nh) * Cn + mi[m]) * Cn + c];
    }
    ent_att[(long)blk * Cn + c] = s / cnt;
}

__global__ void ht_att_k(const float* __restrict__ ent_att, const int* __restrict__ hts,
                         float* __restrict__ ht_att)
{
    const int bp = blockIdx.x;
    const int b = bp / Pn;
    const int hi = hts[bp * 2], ti = hts[bp * 2 + 1];
    const int c = threadIdx.x;
    const float* ha = ent_att + (long)(b * NEn + hi) * NHn * Cn;
    const float* ta = ent_att + (long)(b * NEn + ti) * NHn * Cn;
    float v = 0.f;
    #pragma unroll
    for (int nh = 0; nh < NHn; ++nh) v += ha[nh * Cn + c] * ta[nh * Cn + c];
    v *= (1.f / 12.f);
    __shared__ float red[512];
    red[c] = v; __syncthreads();
    for (int s = 256; s > 0; s >>= 1) { if (c < s) red[c] += red[c + s]; __syncthreads(); }
    ht_att[(long)bp * Cn + c] = v / (red[0] + 1e-5f);
}

__global__ void pool_attn_k(const float* __restrict__ htq, const float* __restrict__ ent_q,
                            const float* __restrict__ ent_emb, const float* __restrict__ mmask,
                            const int* __restrict__ hts, float* __restrict__ hs_att,
                            float* __restrict__ ts_att)
{
    const int bp = blockIdx.x;
    const int side = blockIdx.y;
    const int b = bp / Pn;
    const int e = hts[bp * 2 + side];
    __shared__ float qs[QSn];
    __shared__ float gs[MMn];
    const int tid = threadIdx.x;
    if (tid < QSn) qs[tid] = htq[(long)bp * QSn + tid];
    __syncthreads();
    if (tid < MMn) {
        const float* eq = ent_q + ((long)(b * NEn + e) * MMn + tid) * QSn;
        float d = 0.f;
        for (int i = 0; i < QSn; ++i) d += qs[i] * eq[i];
        const float mk = mmask[(b * NEn + e) * MMn + tid];
        gs[tid] = (mk > 0.f) ? d * SCALE_EMB : kNEG;
    }
    __syncthreads();
    float mx = -1e30f;
    for (int m = 0; m < MMn; ++m) mx = fmaxf(mx, gs[m]);
    float w[MMn]; float ssum = 0.f;
    for (int m = 0; m < MMn; ++m) { w[m] = expf(gs[m] - mx); ssum += w[m]; }
    const float inv = 1.f / ssum;
    const float* emb = ent_emb + (long)(b * NEn + e) * MMn * Hn;
    float* out = (side ? ts_att : hs_att) + (long)bp * Hn;
    for (int h = tid; h < Hn; h += 256) {
        float acc2 = 0.f;
        for (int m = 0; m < MMn; ++m) acc2 += w[m] * emb[m * Hn + h];
        out[h] = acc2 * inv;
    }
}

__global__ void cat2_k(const float* __restrict__ hs_att, const float* __restrict__ ts_att,
                       const float* __restrict__ rs, float* __restrict__ cat_h,
                       float* __restrict__ cat_t)
{
    const long r = blockIdx.x;
    for (int h = threadIdx.x; h < Hn; h += 256) {
        const float rv = rs[r * Hn + h];
        cat_h[r * 1536 + h]       = hs_att[r * Hn + h];
        cat_h[r * 1536 + 768 + h] = rv;
        cat_t[r * 1536 + h]       = ts_att[r * Hn + h];
        cat_t[r * 1536 + 768 + h] = rv;
    }
}

__global__ void catpp_k(const float* __restrict__ pairg, const float* __restrict__ pos_emb,
                        const int* __restrict__ hts, float* __restrict__ catpp)
{
    const long r = blockIdx.x;
    const int hi = hts[r * 2], ti = hts[r * 2 + 1];
    if (threadIdx.x < POSn) {
        catpp[r * 1024 + threadIdx.x]       = pos_emb[hi * POSn + threadIdx.x];
        catpp[r * 1024 + 896 + threadIdx.x] = pos_emb[ti * POSn + threadIdx.x];
    }
    for (int h = threadIdx.x; h < Hn; h += 256)
        catpp[r * 1024 + 128 + h] = pairg[r * Hn + h];
}

__global__ void pair_softmax_k(float* __restrict__ sc, const float* __restrict__ vis)
{
    const long bp = blockIdx.x;
    float* row = sc + bp * Pn;
    const float* vr = vis + bp * Pn;
    const int tid = threadIdx.x;
    __shared__ float red[128];
    float mx = -1e30f;
    for (int q = tid; q < Pn; q += 128) {
        const float v = (vr[q] > 0.f) ? row[q] : kNEG;
        mx = fmaxf(mx, v);
    }
    red[tid] = mx; __syncthreads();
    for (int s = 64; s > 0; s >>= 1) { if (tid < s) red[tid] = fmaxf(red[tid], red[tid + s]); __syncthreads(); }
    mx = red[0]; __syncthreads();
    float sum = 0.f;
    for (int q = tid; q < Pn; q += 128) {
        const float v = (vr[q] > 0.f) ? row[q] : kNEG;
        sum += expf(v - mx);
    }
    red[tid] = sum; __syncthreads();
    for (int s = 64; s > 0; s >>= 1) { if (tid < s) red[tid] += red[tid + s]; __syncthreads(); }
    const float inv = 1.f / red[0];
    for (int q = tid; q < Pn; q += 128) {
        const float v = (vr[q] > 0.f) ? row[q] : kNEG;
        row[q] = expf(v - mx) * inv;
    }
}

__global__ void catfeat_k(const float* __restrict__ hs, const float* __restrict__ ts,
                          const float* __restrict__ pair1, const float* __restrict__ atto,
                          float* __restrict__ catf)
{
    const long r = blockIdx.x;
    for (int h = threadIdx.x; h < Hn; h += 256) {
        catf[r * 2304 + h]        = hs[r * Hn + h];
        catf[r * 2304 + 768 + h]  = ts[r * Hn + h];
        catf[r * 2304 + 1536 + h] = pair1[r * Hn + h] + atto[r * Hn + h];
    }
}

// ---------------- launcher ----------------
extern "C" void kernel_launch(void* const* d_in, const int* in_sizes, int n_in,
                              void* d_out, int out_size)
{
    (void)in_sizes; (void)n_in; (void)out_size;
    const float* seq   = (const float*)d_in[0];
    const float* att   = (const float*)d_in[1];
    const int*   midx  = (const int*)  d_in[2];
    const float* mmask = (const float*)d_in[3];
    const int*   hts   = (const int*)  d_in[4];
    const float* vis   = (const float*)d_in[5];
    const float* Wcq = (const float*)d_in[6],  *bcq = (const float*)d_in[7];
    const float* Weq = (const float*)d_in[8],  *beq = (const float*)d_in[9];
    const float* Whe = (const float*)d_in[10], *bhe = (const float*)d_in[11];
    const float* Wte = (const float*)d_in[12], *bte = (const float*)d_in[13];
    const float* Wbl = (const float*)d_in[14], *bbl = (const float*)d_in[15];
    const float* Wpp = (const float*)d_in[16], *bpp = (const float*)d_in[17];
    const float* Wgq = (const float*)d_in[18];
    const float* Wgk = (const float*)d_in[19];
    const float* Wgv = (const float*)d_in[20];
    const float* Wp1 = (const float*)d_in[21], *bp1 = (const float*)d_in[22];
    const float* Wp2 = (const float*)d_in[23], *bp2 = (const float*)d_in[24];
    const float* pos = (const float*)d_in[25];
    float* out = (float*)d_out;

    float* base = nullptr;
    cudaGetSymbolAddress((void**)&base, g_scratch);
    float* ent_emb = base + OFF_ENT_EMB;
    float* ent_att = base + OFF_ENT_ATT;
    float* ent_q   = base + OFF_ENT_Q;
    float* ht_att  = base + OFF_HT_ATT;
    float* rs      = base + OFF_RS;
    float* htqb    = base + OFF_HTQ;
    float* hs_att  = base + OFF_HS_ATT;
    float* ts_att  = base + OFF_TS_ATT;
    float* cat_h   = base + OFF_CAT_H;
    float* hs_t    = base + OFF_HS;
    float* ts_t    = base + OFF_TS;
    float* pairg   = base + OFF_PAIRG;
    float* catpp   = base + OFF_CATPP;
    float* pair1   = base + OFF_PAIR1;
    float* qb      = base + OFF_QB;
    float* kb      = base + OFF_KB;
    float* vb      = base + OFF_VB;
    float* scb     = base + OFF_SC;
    float* atto    = base + OFF_ATTO;
    float* catf    = base + OFF_CATF;
    float* h1      = base + OFF_H1;
    float* wcat    = base + OFF_WCAT;
    float* wqkv    = base + OFF_WQKV;
    float* wb      = base + OFF_WB;

    cudaFuncSetAttribute(gemm_tc<false,false,false>, cudaFuncAttributeMaxDynamicSharedMemorySize, GT_SMEM);
    cudaFuncSetAttribute(gemm_tc<false,true,false>,  cudaFuncAttributeMaxDynamicSharedMemorySize, GT_SMEM);
    cudaFuncSetAttribute(gemm_tc<false,true,true>,   cudaFuncAttributeMaxDynamicSharedMemorySize, GT_SMEM);
    cudaFuncSetAttribute(gemm_tc<true,false,false>,  cudaFuncAttributeMaxDynamicSharedMemorySize, GT_SMEM);
    cudaFuncSetAttribute(bilinear_tc, cudaFuncAttributeMaxDynamicSharedMemorySize, BL_SMEM);

    // 0) pack batched weights/biases for z-batched launches
    cudaMemcpyAsync(wcat,              Whe, 1536UL*768*4, cudaMemcpyDeviceToDevice);
    cudaMemcpyAsync(wcat + 1536UL*768, Wte, 1536UL*768*4, cudaMemcpyDeviceToDevice);
    cudaMemcpyAsync(wqkv,              Wgq, 768UL*768*4,  cudaMemcpyDeviceToDevice);
    cudaMemcpyAsync(wqkv + 768UL*768,  Wgk, 768UL*768*4,  cudaMemcpyDeviceToDevice);
    cudaMemcpyAsync(wqkv + 2UL*768*768,Wgv, 768UL*768*4,  cudaMemcpyDeviceToDevice);
    cudaMemcpyAsync(wb,                bhe, 768UL*4,      cudaMemcpyDeviceToDevice);
    cudaMemcpyAsync(wb + 768,          bte, 768UL*4,      cudaMemcpyDeviceToDevice);

    // 1) entity gathers
    ent_emb_k<<<Bn * NEn * MMn, 256>>>(seq, midx, mmask, ent_emb);
    ent_att_k<<<Bn * NEn * NHn, 512>>>(att, midx, mmask, ent_att);
    // 2) pair context attention
    ht_att_k<<<BPn, 512>>>(ent_att, hts, ht_att);
    // 3) rs = ht_att @ seq (batched)
    gemm_tc<false,false,false><<<dim3(12, 6, 4), 256, GT_SMEM>>>(ht_att, seq, nullptr, rs,
        Pn, Hn, Cn, Cn, Hn, Hn, 380L*512, 512L*768, 380L*768, 1.f, 0L);
    // 4) htq, ent_q
    gemm_tc<false,true,false><<<dim3(2, 24, 1), 256, GT_SMEM>>>(rs, Wcq, bcq, htqb,
        BPn, QSn, Hn, Hn, QSn, QSn, 0, 0, 0, 1.f, 0L);
    gemm_tc<false,true,false><<<dim3(2, 29, 1), 256, GT_SMEM>>>(ent_emb, Weq, beq, ent_q,
        1840, QSn, Hn, Hn, QSn, QSn, 0, 0, 0, 1.f, 0L);
    // 5) mention-pool softmax
    pool_attn_k<<<dim3(BPn, 2), 256>>>(htqb, ent_q, ent_emb, mmask, hts, hs_att, ts_att);
    // 6) hs/ts projections — ONE z=2 batched launch (per-z bias)
    cat2_k<<<BPn, 256>>>(hs_att, ts_att, rs, cat_h, base + OFF_CAT_T);
    gemm_tc<false,true,true><<<dim3(12, 24, 2), 256, GT_SMEM>>>(cat_h, wcat, wb, hs_t,
        BPn, EMBn, 1536, 1536, EMBn, EMBn, 1520L*1536, 1536L*768, 1520L*768, 1.f, 768L);
    // 7) grouped bilinear (bulk-copy W stream)
    bilinear_tc<<<dim3(12, 12), 512, BL_SMEM>>>(hs_t, ts_t, Wbl, bbl, pairg, BPn);
    // 8) pos concat + Wpp
    catpp_k<<<BPn, 256>>>(pairg, pos, hts, catpp);
    gemm_tc<false,true,true><<<dim3(12, 24, 1), 256, GT_SMEM>>>(catpp, Wpp, bpp, pair1,
        BPn, EMBn, 1024, 1024, EMBn, EMBn, 0, 0, 0, 1.f, 0L);
    // 9) pair-graph attention: q/k/v in ONE batched launch (z=3)
    gemm_tc<false,false,false><<<dim3(12, 24, 3), 256, GT_SMEM>>>(pair1, wqkv, nullptr, qb,
        BPn, EMBn, EMBn, EMBn, EMBn, EMBn, 0, 768L*768, 1520L*768, 1.f, 0L);
    gemm_tc<true,false,false><<<dim3(6, 6, 4), 256, GT_SMEM>>>(qb, kb, nullptr, scb,
        Pn, Pn, EMBn, EMBn, EMBn, Pn, 380L*768, 380L*768, 380L*380, SCALE_EMB, 0L);
    pair_softmax_k<<<BPn, 128>>>(scb, vis);
    gemm_tc<false,false,false><<<dim3(12, 6, 4), 256, GT_SMEM>>>(scb, vb, nullptr, atto,
        Pn, EMBn, Pn, Pn, EMBn, EMBn, 380L*380, 380L*768, 380L*768, 1.f, 0L);
    // 10) classifier head
    catfeat_k<<<BPn, 256>>>(hs_t, ts_t, pair1, atto, catf);
    gemm_tc<false,true,true><<<dim3(12, 24, 1), 256, GT_SMEM>>>(catf, Wp1, bp1, h1,
        BPn, EMBn, 2304, 2304, EMBn, EMBn, 0, 0, 0, 1.f, 0L);
    gemm_tc<false,true,false><<<dim3(2, 24, 1), 256, GT_SMEM>>>(h1, Wp2, bp2, out,
        BPn, NCLSn, EMBn, EMBn, NCLSn, NCLSn, 0, 0, 0, 1.f, 0L);
}

// round 11
// speedup vs baseline: 1.0125x; 1.0125x over previous
#include <cuda_runtime.h>
#include <stdint.h>
#include <math.h>

// ---------------- problem constants ----------------
#define Bn   4
#define Cn   512
#define Hn   768
#define NHn  12
#define NEn  20
#define MMn  23
#define Pn   380
#define BPn  1520
#define QSn  128
#define EMBn 768
#define NBn  12
#define BLKn 64
#define NCLSn 97
#define POSn 128

static __device__ __constant__ float kNEG = -10000.0f;
#define SCALE_EMB 0.03608439182435161f   // 1/sqrt(768)

// ---------------- scratch ----------------
#define OFF_ENT_EMB 0UL
#define OFF_ENT_ATT (OFF_ENT_EMB + 1840UL*768)
#define OFF_ENT_Q   (OFF_ENT_ATT + 960UL*512)
#define OFF_HT_ATT  (OFF_ENT_Q   + 1840UL*128)
#define OFF_RS      (OFF_HT_ATT  + 1520UL*512)
#define OFF_HTQ     (OFF_RS      + 1520UL*768)
#define OFF_HS_ATT  (OFF_HTQ     + 1520UL*128)
#define OFF_TS_ATT  (OFF_HS_ATT  + 1520UL*768)
#define OFF_CAT_H   (OFF_TS_ATT  + 1520UL*768)
#define OFF_CAT_T   (OFF_CAT_H   + 1520UL*1536)
#define OFF_HS      (OFF_CAT_T   + 1520UL*1536)
#define OFF_TS      (OFF_HS      + 1520UL*768)
#define OFF_PAIRG   (OFF_TS      + 1520UL*768)
#define OFF_CATPP   (OFF_PAIRG   + 1520UL*768)
#define OFF_PAIR1   (OFF_CATPP   + 1520UL*1024)
#define OFF_QB      (OFF_PAIR1   + 1520UL*768)
#define OFF_KB      (OFF_QB      + 1520UL*768)
#define OFF_VB      (OFF_KB      + 1520UL*768)
#define OFF_SC      (OFF_VB      + 1520UL*768)
#define OFF_ATTO    (OFF_SC      + 4UL*380*380)
#define OFF_CATF    (OFF_ATTO    + 1520UL*768)
#define OFF_H1      (OFF_CATF    + 1520UL*2304)
#define OFF_WCAT    (OFF_H1      + 1520UL*768)
#define OFF_WQKV    (OFF_WCAT    + 2UL*1536*768)
#define OFF_WB      (OFF_WQKV    + 3UL*768*768)
#define SCRATCH_TOTAL (OFF_WB    + 2UL*768)

__device__ float g_scratch[SCRATCH_TOTAL];

// ---------------- helpers ----------------
__device__ __forceinline__ uint32_t f2tf32(float x) {
    uint32_t r; asm("cvt.rna.tf32.f32 %0, %1;" : "=r"(r) : "f"(x)); return r;
}
__device__ __forceinline__ void mma_tf32(float* c, const uint32_t* a, const uint32_t* b) {
    asm volatile("mma.sync.aligned.m16n8k8.row.col.f32.tf32.tf32.f32 "
        "{%0,%1,%2,%3}, {%4,%5,%6,%7}, {%8,%9}, {%0,%1,%2,%3};"
        : "+f"(c[0]), "+f"(c[1]), "+f"(c[2]), "+f"(c[3])
        : "r"(a[0]), "r"(a[1]), "r"(a[2]), "r"(a[3]), "r"(b[0]), "r"(b[1]));
}
__device__ __forceinline__ void cp16(void* s, const void* g, int sz) {
    uint32_t sa = (uint32_t)__cvta_generic_to_shared(s);
    asm volatile("cp.async.cg.shared.global [%0], [%1], 16, %2;" :: "r"(sa), "l"(g), "r"(sz));
}
__device__ __forceinline__ void cp4(void* s, const void* g, int sz) {
    uint32_t sa = (uint32_t)__cvta_generic_to_shared(s);
    asm volatile("cp.async.ca.shared.global [%0], [%1], 4, %2;" :: "r"(sa), "l"(g), "r"(sz));
}
__device__ __forceinline__ void cp_commit() { asm volatile("cp.async.commit_group;"); }
template<int Ng> __device__ __forceinline__ void cp_wait() {
    asm volatile("cp.async.wait_group %0;" :: "n"(Ng));
}

// ---------------- tf32 GEMM: 64x64xBK32, 256 thr (8 warps of 16x32), 3-stage cp.async ----------------
#define GT_BM 64
#define GT_BN 64
#define GT_BK 32
#define GT_SMEM (3 * 2304 * 2 * 4)

template<bool TRANSB, bool BIAS, bool TANH>
__global__ __launch_bounds__(256, 2)
void gemm_tc(const float* __restrict__ A, const float* __restrict__ Bm,
             const float* __restrict__ bias, float* __restrict__ C,
             int M, int N, int K, int lda, int ldb, int ldc,
             long sA, long sB, long sC, float alpha, long sBias)
{
    extern __shared__ float sm[];
    float* As = sm;                     // [3][64][36]
    float* Bs = sm + 3 * 2304;          // [3][32][72] (!T) or [3][64][36] (T)
    const int tid = threadIdx.x;
    const int wid = tid >> 5, lane = tid & 31;
    const int gid = lane >> 2, tig = lane & 3;
    const int m0 = blockIdx.y * GT_BM, n0 = blockIdx.x * GT_BN;
    A  += (long)blockIdx.z * sA;
    Bm += (long)blockIdx.z * sB;
    C  += (long)blockIdx.z * sC;
    if (BIAS) bias += (long)blockIdx.z * sBias;
    const int wm0 = (wid & 3) * 16, wn0 = (wid >> 2) * 32;
    float acc[4][4] = {};

    const int ar = tid >> 2, akc = (tid & 3) * 8;
    const int bkr = tid >> 3, bnc = (tid & 7) * 8;
    const bool a_ok = (m0 + ar) < M;
    const bool b4 = (!TRANSB) && (((ldb & 3) != 0) || ((N & 3) != 0));
    const int nk = (K + GT_BK - 1) / GT_BK;

    auto issueA = [&](int kt, int st) {
        float* dst = As + st * 2304 + ar * 36 + akc;
        const float* src = A + (long)(m0 + ar) * lda + kt * GT_BK + akc;
        #pragma unroll
        for (int q = 0; q < 2; ++q) {
            int sz = (a_ok && (kt * GT_BK + akc + 4 * q) < K) ? 16 : 0;
            cp16(dst + 4 * q, src + 4 * q, sz);
        }
    };
    auto issueB = [&](int kt, int st) {
        if (!TRANSB) {
            float* dst = Bs + st * 2304 + bkr * 72 + bnc;
            const float* src = Bm + (long)(kt * GT_BK + bkr) * ldb + n0 + bnc;
            const bool kok = (kt * GT_BK + bkr) < K;
            if (!b4) {
                #pragma unroll
                for (int q = 0; q < 2; ++q) {
                    int sz = (kok && (n0 + bnc + 4 * q) < N) ? 16 : 0;
                    cp16(dst + 4 * q, src + 4 * q, sz);
                }
            } else {
                #pragma unroll
                for (int e = 0; e < 8; ++e) {
                    int sz = (kok && (n0 + bnc + e) < N) ? 4 : 0;
                    cp4(dst + e, src + e, sz);
                }
            }
        } else {
            float* dst = Bs + st * 2304 + ar * 36 + akc;
            const float* src = Bm + (long)(n0 + ar) * ldb + kt * GT_BK + akc;
            const bool nok = (n0 + ar) < N;
            #pragma unroll
            for (int q = 0; q < 2; ++q) {
                int sz = (nok && (kt * GT_BK + akc + 4 * q) < K) ? 16 : 0;
                cp16(dst + 4 * q, src + 4 * q, sz);
            }
        }
    };

    issueA(0, 0); issueB(0, 0); cp_commit();
    if (nk > 1) { issueA(1, 1); issueB(1, 1); }
    cp_commit();

    int st = 0;
    for (int kt = 0; kt < nk; ++kt) {
        cp_wait<1>();
        __syncthreads();
        const int ktn = kt + 2;
        if (ktn < nk) {
            const int stn = (st + 2 >= 3) ? st - 1 : st + 2;
            issueA(ktn, stn); issueB(ktn, stn);
        }
        cp_commit();
        const float* Ac = As + st * 2304;
        const float* Bc = Bs + st * 2304;
        #pragma unroll
        for (int kk = 0; kk < GT_BK; kk += 8) {
            uint32_t af[4], bf[4][2];
            af[0] = f2tf32(Ac[(wm0 + gid) * 36 + kk + tig]);
            af[1] = f2tf32(Ac[(wm0 + 8 + gid) * 36 + kk + tig]);
            af[2] = f2tf32(Ac[(wm0 + gid) * 36 + kk + tig + 4]);
            af[3] = f2tf32(Ac[(wm0 + 8 + gid) * 36 + kk + tig + 4]);
            #pragma unroll
            for (int nf = 0; nf < 4; ++nf) {
                const int c = wn0 + nf * 8 + gid;
                if (!TRANSB) {
                    bf[nf][0] = f2tf32(Bc[(kk + tig) * 72 + c]);
                    bf[nf][1] = f2tf32(Bc[(kk + tig + 4) * 72 + c]);
                } else {
                    bf[nf][0] = f2tf32(Bc[c * 36 + kk + tig]);
                    bf[nf][1] = f2tf32(Bc[c * 36 + kk + tig + 4]);
                }
            }
            #pragma unroll
            for (int nf = 0; nf < 4; ++nf)
                mma_tf32(acc[nf], af, bf[nf]);
        }
        st = (st + 1 >= 3) ? 0 : st + 1;
    }
    // ---- epilogue ----
    #pragma unroll
    for (int nf = 0; nf < 4; ++nf) {
        const int r = m0 + wm0 + gid;
        const int c = n0 + wn0 + nf * 8 + tig * 2;
        #pragma unroll
        for (int half = 0; half < 2; ++half) {
            const int rr = r + half * 8;
            if (rr >= M) continue;
            #pragma unroll
            for (int j = 0; j < 2; ++j) {
                const int cc = c + j;
                if (cc >= N) continue;
                float v = acc[nf][half * 2 + j] * alpha;
                if (BIAS) v += bias[cc];
                if (TANH) v = tanhf(v);
                C[(long)rr * ldc + cc] = v;
            }
        }
    }
}

// ---------------- bilinear: 512 thr, M-tile 128, W fragments loaded global->register ----------------
// C[m,n] = sum_{nb,i,j} Hs[m,nb*64+i]*Ts[m,nb*64+j]*W[(nb*4096+i*64+j), n] + bias[n]
// No W smem staging, no per-step barriers: warps drift within an nb-block.
#define BL_SMEM (2 * 128 * 68 * 4)
__global__ __launch_bounds__(512)
void bilinear_tc(const float* __restrict__ Hs, const float* __restrict__ Ts,
                 const float* __restrict__ W, const float* __restrict__ bias,
                 float* __restrict__ C, int M)
{
    extern __shared__ float sm[];
    float* bh = sm;                      // [128][68]
    float* bt = sm + 128 * 68;           // [128][68]
    const int tid = threadIdx.x;
    const int wid = tid >> 5, lane = tid & 31;
    const int gid = lane >> 2, tig = lane & 3;
    const int m0 = blockIdx.y * 128, n0 = blockIdx.x * 64;
    const int wm0 = (wid & 3) * 32, wn0 = (wid >> 2) * 16;   // 16 warps: 4m x 4n
    float acc[2][2][4] = {};
    const int lr = tid >> 2, lc = (tid & 3) * 16;
    const bool lok = (m0 + lr) < M;
    uint32_t btf[2][8][4];

#define LOADHT(nb_) { \
    const float* hp = Hs + (long)(m0 + lr) * 768 + (nb_) * 64 + lc; \
    const float* tp = Ts + (long)(m0 + lr) * 768 + (nb_) * 64 + lc; \
    _Pragma("unroll") for (int q_ = 0; q_ < 4; ++q_) { \
        float4 hv = lok ? *(const float4*)(hp + 4 * q_) : make_float4(0, 0, 0, 0); \
        float4 tv = lok ? *(const float4*)(tp + 4 * q_) : make_float4(0, 0, 0, 0); \
        *(float4*)&bh[lr * 68 + lc + 4 * q_] = hv; \
        *(float4*)&bt[lr * 68 + lc + 4 * q_] = tv; } }

#define CACHEBT() { \
    _Pragma("unroll") for (int mf_ = 0; mf_ < 2; ++mf_) { const int r0_ = wm0 + mf_ * 16; \
        _Pragma("unroll") for (int j0_ = 0; j0_ < 8; ++j0_) { \
            btf[mf_][j0_][0] = f2tf32(bt[(r0_ + gid) * 68 + j0_ * 8 + tig]); \
            btf[mf_][j0_][1] = f2tf32(bt[(r0_ + 8 + gid) * 68 + j0_ * 8 + tig]); \
            btf[mf_][j0_][2] = f2tf32(bt[(r0_ + gid) * 68 + j0_ * 8 + tig + 4]); \
            btf[mf_][j0_][3] = f2tf32(bt[(r0_ + 8 + gid) * 68 + j0_ * 8 + tig + 4]); } } }

    for (int nb = 0; nb < NBn; ++nb) {
        __syncthreads();                 // all warps finished reading prior bh/bt
        LOADHT(nb);
        __syncthreads();                 // new bh/bt visible
        CACHEBT();
        for (int ii = 0; ii < 64; ++ii) {
            // this warp's W fragment base: rows (nb*64+ii)*64 .. +63, cols n0+wn0..+15
            const float* Wp = W + ((long)(nb * 64 + ii) * 64) * 768 + n0 + wn0;
            float D[2][2][4] = {};
            #pragma unroll
            for (int half = 0; half < 2; ++half) {
                // batch-load 16 W values (4 j0 x 2 nf x 2) -> MLP 16
                float wv[4][2][2];
                #pragma unroll
                for (int jj = 0; jj < 4; ++jj) {
                    const int j0 = half * 4 + jj;
                    #pragma unroll
                    for (int nf = 0; nf < 2; ++nf) {
                        wv[jj][nf][0] = __ldg(Wp + (j0 * 8 + tig) * 768 + nf * 8 + gid);
                        wv[jj][nf][1] = __ldg(Wp + (j0 * 8 + tig + 4) * 768 + nf * 8 + gid);
                    }
                }
                #pragma unroll
                for (int jj = 0; jj < 4; ++jj) {
                    const int j0 = half * 4 + jj;
                    uint32_t bfp[2][2];
                    bfp[0][0] = f2tf32(wv[jj][0][0]); bfp[0][1] = f2tf32(wv[jj][0][1]);
                    bfp[1][0] = f2tf32(wv[jj][1][0]); bfp[1][1] = f2tf32(wv[jj][1][1]);
                    #pragma unroll
                    for (int mf = 0; mf < 2; ++mf)
                        #pragma unroll
                        for (int nf = 0; nf < 2; ++nf)
                            mma_tf32(D[mf][nf], btf[mf][j0], bfp[nf]);
                }
            }
            #pragma unroll
            for (int mf = 0; mf < 2; ++mf) {
                const float b0 = bh[(wm0 + mf * 16 + gid) * 68 + ii];
                const float b1 = bh[(wm0 + mf * 16 + 8 + gid) * 68 + ii];
                #pragma unroll
                for (int nf = 0; nf < 2; ++nf) {
                    acc[mf][nf][0] = fmaf(b0, D[mf][nf][0], acc[mf][nf][0]);
                    acc[mf][nf][1] = fmaf(b0, D[mf][nf][1], acc[mf][nf][1]);
                    acc[mf][nf][2] = fmaf(b1, D[mf][nf][2], acc[mf][nf][2]);
                    acc[mf][nf][3] = fmaf(b1, D[mf][nf][3], acc[mf][nf][3]);
                }
            }
        }
    }
#undef LOADHT
#undef CACHEBT
    #pragma unroll
    for (int mf = 0; mf < 2; ++mf) {
        #pragma unroll
        for (int nf = 0; nf < 2; ++nf) {
            const int r = m0 + wm0 + mf * 16 + gid;
            const int c = n0 + wn0 + nf * 8 + tig * 2;
            if (r < M) {
                C[(long)r * 768 + c]     = acc[mf][nf][0] + bias[c];
                C[(long)r * 768 + c + 1] = acc[mf][nf][1] + bias[c + 1];
            }
            if (r + 8 < M) {
                C[(long)(r + 8) * 768 + c]     = acc[mf][nf][2] + bias[c];
                C[(long)(r + 8) * 768 + c + 1] = acc[mf][nf][3] + bias[c + 1];
            }
        }
    }
}

// ---------------- small fused kernels ----------------
__global__ void ent_emb_k(const float* __restrict__ seq, const int* __restrict__ midx,
                          const float* __restrict__ mmask, float* __restrict__ ent_emb)
{
    const int blk = blockIdx.x;
    const int b = blk / (MMn * NEn);
    const int idx = midx[blk];
    const float mask = mmask[blk];
    const float* src = seq + ((long)b * Cn + idx) * Hn;
    float* dst = ent_emb + (long)blk * Hn;
    for (int h = threadIdx.x; h < Hn; h += 256) dst[h] = mask * src[h];
}

__global__ void ent_att_k(const float* __restrict__ att, const int* __restrict__ midx,
                          const float* __restrict__ mmask, float* __restrict__ ent_att)
{
    const int blk = blockIdx.x;
    const int nh = blk % NHn;
    const int e  = (blk / NHn) % NEn;
    const int b  = blk / (NHn * NEn);
    const int c  = threadIdx.x;
    const int* mi = midx + (b * NEn + e) * MMn;
    const float* mk = mmask + (b * NEn + e) * MMn;
    float cnt = 0.f, s = 0.f;
    for (int m = 0; m < MMn; ++m) {
        const float w = mk[m];
        cnt += w;
        s += w * att[(((long)b * NHn + nh) * Cn + mi[m]) * Cn + c];
    }
    ent_att[(long)blk * Cn + c] = s / cnt;
}

__global__ void ht_att_k(const float* __restrict__ ent_att, const int* __restrict__ hts,
                         float* __restrict__ ht_att)
{
    const int bp = blockIdx.x;
    const int b = bp / Pn;
    const int hi = hts[bp * 2], ti = hts[bp * 2 + 1];
    const int c = threadIdx.x;
    const float* ha = ent_att + (long)(b * NEn + hi) * NHn * Cn;
    const float* ta = ent_att + (long)(b * NEn + ti) * NHn * Cn;
    float v = 0.f;
    #pragma unroll
    for (int nh = 0; nh < NHn; ++nh) v += ha[nh * Cn + c] * ta[nh * Cn + c];
    v *= (1.f / 12.f);
    __shared__ float red[512];
    red[c] = v; __syncthreads();
    for (int s = 256; s > 0; s >>= 1) { if (c < s) red[c] += red[c + s]; __syncthreads(); }
    ht_att[(long)bp * Cn + c] = v / (red[0] + 1e-5f);
}

__global__ void pool_attn_k(const float* __restrict__ htq, const float* __restrict__ ent_q,
                            const float* __restrict__ ent_emb, const float* __restrict__ mmask,
                            const int* __restrict__ hts, float* __restrict__ hs_att,
                            float* __restrict__ ts_att)
{
    const int bp = blockIdx.x;
    const int side = blockIdx.y;
    const int b = bp / Pn;
    const int e = hts[bp * 2 + side];
    __shared__ float qs[QSn];
    __shared__ float gs[MMn];
    const int tid = threadIdx.x;
    if (tid < QSn) qs[tid] = htq[(long)bp * QSn + tid];
    __syncthreads();
    if (tid < MMn) {
        const float* eq = ent_q + ((long)(b * NEn + e) * MMn + tid) * QSn;
        float d = 0.f;
        for (int i = 0; i < QSn; ++i) d += qs[i] * eq[i];
        const float mk = mmask[(b * NEn + e) * MMn + tid];
        gs[tid] = (mk > 0.f) ? d * SCALE_EMB : kNEG;
    }
    __syncthreads();
    float mx = -1e30f;
    for (int m = 0; m < MMn; ++m) mx = fmaxf(mx, gs[m]);
    float w[MMn]; float ssum = 0.f;
    for (int m = 0; m < MMn; ++m) { w[m] = expf(gs[m] - mx); ssum += w[m]; }
    const float inv = 1.f / ssum;
    const float* emb = ent_emb + (long)(b * NEn + e) * MMn * Hn;
    float* out = (side ? ts_att : hs_att) + (long)bp * Hn;
    for (int h = tid; h < Hn; h += 256) {
        float acc2 = 0.f;
        for (int m = 0; m < MMn; ++m) acc2 += w[m] * emb[m * Hn + h];
        out[h] = acc2 * inv;
    }
}

__global__ void cat2_k(const float* __restrict__ hs_att, const float* __restrict__ ts_att,
                       const float* __restrict__ rs, float* __restrict__ cat_h,
                       float* __restrict__ cat_t)
{
    const long r = blockIdx.x;
    for (int h = threadIdx.x; h < Hn; h += 256) {
        const float rv = rs[r * Hn + h];
        cat_h[r * 1536 + h]       = hs_att[r * Hn + h];
        cat_h[r * 1536 + 768 + h] = rv;
        cat_t[r * 1536 + h]       = ts_att[r * Hn + h];
        cat_t[r * 1536 + 768 + h] = rv;
    }
}

__global__ void catpp_k(const float* __restrict__ pairg, const float* __restrict__ pos_emb,
                        const int* __restrict__ hts, float* __restrict__ catpp)
{
    const long r = blockIdx.x;
    const int hi = hts[r * 2], ti = hts[r * 2 + 1];
    if (threadIdx.x < POSn) {
        catpp[r * 1024 + threadIdx.x]       = pos_emb[hi * POSn + threadIdx.x];
        catpp[r * 1024 + 896 + threadIdx.x] = pos_emb[ti * POSn + threadIdx.x];
    }
    for (int h = threadIdx.x; h < Hn; h += 256)
        catpp[r * 1024 + 128 + h] = pairg[r * Hn + h];
}

__global__ void pair_softmax_k(float* __restrict__ sc, const float* __restrict__ vis)
{
    const long bp = blockIdx.x;
    float* row = sc + bp * Pn;
    const float* vr = vis + bp * Pn;
    const int tid = threadIdx.x;
    __shared__ float red[128];
    float mx = -1e30f;
    for (int q = tid; q < Pn; q += 128) {
        const float v = (vr[q] > 0.f) ? row[q] : kNEG;
        mx = fmaxf(mx, v);
    }
    red[tid] = mx; __syncthreads();
    for (int s = 64; s > 0; s >>= 1) { if (tid < s) red[tid] = fmaxf(red[tid], red[tid + s]); __syncthreads(); }
    mx = red[0]; __syncthreads();
    float sum = 0.f;
    for (int q = tid; q < Pn; q += 128) {
        const float v = (vr[q] > 0.f) ? row[q] : kNEG;
        sum += expf(v - mx);
    }
    red[tid] = sum; __syncthreads();
    for (int s = 64; s > 0; s >>= 1) { if (tid < s) red[tid] += red[tid + s]; __syncthreads(); }
    const float inv = 1.f / red[0];
    for (int q = tid; q < Pn; q += 128) {
        const float v = (vr[q] > 0.f) ? row[q] : kNEG;
        row[q] = expf(v - mx) * inv;
    }
}

__global__ void catfeat_k(const float* __restrict__ hs, const float* __restrict__ ts,
                          const float* __restrict__ pair1, const float* __restrict__ atto,
                          float* __restrict__ catf)
{
    const long r = blockIdx.x;
    for (int h = threadIdx.x; h < Hn; h += 256) {
        catf[r * 2304 + h]        = hs[r * Hn + h];
        catf[r * 2304 + 768 + h]  = ts[r * Hn + h];
        catf[r * 2304 + 1536 + h] = pair1[r * Hn + h] + atto[r * Hn + h];
    }
}

// ---------------- launcher ----------------
extern "C" void kernel_launch(void* const* d_in, const int* in_sizes, int n_in,
                              void* d_out, int out_size)
{
    (void)in_sizes; (void)n_in; (void)out_size;
    const float* seq   = (const float*)d_in[0];
    const float* att   = (const float*)d_in[1];
    const int*   midx  = (const int*)  d_in[2];
    const float* mmask = (const float*)d_in[3];
    const int*   hts   = (const int*)  d_in[4];
    const float* vis   = (const float*)d_in[5];
    const float* Wcq = (const float*)d_in[6],  *bcq = (const float*)d_in[7];
    const float* Weq = (const float*)d_in[8],  *beq = (const float*)d_in[9];
    const float* Whe = (const float*)d_in[10], *bhe = (const float*)d_in[11];
    const float* Wte = (const float*)d_in[12], *bte = (const float*)d_in[13];
    const float* Wbl = (const float*)d_in[14], *bbl = (const float*)d_in[15];
    const float* Wpp = (const float*)d_in[16], *bpp = (const float*)d_in[17];
    const float* Wgq = (const float*)d_in[18];
    const float* Wgk = (const float*)d_in[19];
    const float* Wgv = (const float*)d_in[20];
    const float* Wp1 = (const float*)d_in[21], *bp1 = (const float*)d_in[22];
    const float* Wp2 = (const float*)d_in[23], *bp2 = (const float*)d_in[24];
    const float* pos = (const float*)d_in[25];
    float* out = (float*)d_out;

    float* base = nullptr;
    cudaGetSymbolAddress((void**)&base, g_scratch);
    float* ent_emb = base + OFF_ENT_EMB;
    float* ent_att = base + OFF_ENT_ATT;
    float* ent_q   = base + OFF_ENT_Q;
    float* ht_att  = base + OFF_HT_ATT;
    float* rs      = base + OFF_RS;
    float* htqb    = base + OFF_HTQ;
    float* hs_att  = base + OFF_HS_ATT;
    float* ts_att  = base + OFF_TS_ATT;
    float* cat_h   = base + OFF_CAT_H;
    float* hs_t    = base + OFF_HS;
    float* ts_t    = base + OFF_TS;
    float* pairg   = base + OFF_PAIRG;
    float* catpp   = base + OFF_CATPP;
    float* pair1   = base + OFF_PAIR1;
    float* qb      = base + OFF_QB;
    float* kb      = base + OFF_KB;
    float* vb      = base + OFF_VB;
    float* scb     = base + OFF_SC;
    float* atto    = base + OFF_ATTO;
    float* catf    = base + OFF_CATF;
    float* h1      = base + OFF_H1;
    float* wcat    = base + OFF_WCAT;
    float* wqkv    = base + OFF_WQKV;
    float* wb      = base + OFF_WB;

    cudaFuncSetAttribute(gemm_tc<false,false,false>, cudaFuncAttributeMaxDynamicSharedMemorySize, GT_SMEM);
    cudaFuncSetAttribute(gemm_tc<false,true,false>,  cudaFuncAttributeMaxDynamicSharedMemorySize, GT_SMEM);
    cudaFuncSetAttribute(gemm_tc<false,true,true>,   cudaFuncAttributeMaxDynamicSharedMemorySize, GT_SMEM);
    cudaFuncSetAttribute(gemm_tc<true,false,false>,  cudaFuncAttributeMaxDynamicSharedMemorySize, GT_SMEM);
    cudaFuncSetAttribute(bilinear_tc, cudaFuncAttributeMaxDynamicSharedMemorySize, BL_SMEM);

    // 0) pack batched weights/biases for z-batched launches
    cudaMemcpyAsync(wcat,              Whe, 1536UL*768*4, cudaMemcpyDeviceToDevice);
    cudaMemcpyAsync(wcat + 1536UL*768, Wte, 1536UL*768*4, cudaMemcpyDeviceToDevice);
    cudaMemcpyAsync(wqkv,              Wgq, 768UL*768*4,  cudaMemcpyDeviceToDevice);
    cudaMemcpyAsync(wqkv + 768UL*768,  Wgk, 768UL*768*4,  cudaMemcpyDeviceToDevice);
    cudaMemcpyAsync(wqkv + 2UL*768*768,Wgv, 768UL*768*4,  cudaMemcpyDeviceToDevice);
    cudaMemcpyAsync(wb,                bhe, 768UL*4,      cudaMemcpyDeviceToDevice);
    cudaMemcpyAsync(wb + 768,          bte, 768UL*4,      cudaMemcpyDeviceToDevice);

    // 1) entity gathers
    ent_emb_k<<<Bn * NEn * MMn, 256>>>(seq, midx, mmask, ent_emb);
    ent_att_k<<<Bn * NEn * NHn, 512>>>(att, midx, mmask, ent_att);
    // 2) pair context attention
    ht_att_k<<<BPn, 512>>>(ent_att, hts, ht_att);
    // 3) rs = ht_att @ seq (batched)
    gemm_tc<false,false,false><<<dim3(12, 6, 4), 256, GT_SMEM>>>(ht_att, seq, nullptr, rs,
        Pn, Hn, Cn, Cn, Hn, Hn, 380L*512, 512L*768, 380L*768, 1.f, 0L);
    // 4) htq, ent_q
    gemm_tc<false,true,false><<<dim3(2, 24, 1), 256, GT_SMEM>>>(rs, Wcq, bcq, htqb,
        BPn, QSn, Hn, Hn, QSn, QSn, 0, 0, 0, 1.f, 0L);
    gemm_tc<false,true,false><<<dim3(2, 29, 1), 256, GT_SMEM>>>(ent_emb, Weq, beq, ent_q,
        1840, QSn, Hn, Hn, QSn, QSn, 0, 0, 0, 1.f, 0L);
    // 5) mention-pool softmax
    pool_attn_k<<<dim3(BPn, 2), 256>>>(htqb, ent_q, ent_emb, mmask, hts, hs_att, ts_att);
    // 6) hs/ts projections — ONE z=2 batched launch (per-z bias)
    cat2_k<<<BPn, 256>>>(hs_att, ts_att, rs, cat_h, base + OFF_CAT_T);
    gemm_tc<false,true,true><<<dim3(12, 24, 2), 256, GT_SMEM>>>(cat_h, wcat, wb, hs_t,
        BPn, EMBn, 1536, 1536, EMBn, EMBn, 1520L*1536, 1536L*768, 1520L*768, 1.f, 768L);
    // 7) grouped bilinear (direct-LDG W fragments)
    bilinear_tc<<<dim3(12, 12), 512, BL_SMEM>>>(hs_t, ts_t, Wbl, bbl, pairg, BPn);
    // 8) pos concat + Wpp
    catpp_k<<<BPn, 256>>>(pairg, pos, hts, catpp);
    gemm_tc<false,true,true><<<dim3(12, 24, 1), 256, GT_SMEM>>>(catpp, Wpp, bpp, pair1,
        BPn, EMBn, 1024, 1024, EMBn, EMBn, 0, 0, 0, 1.f, 0L);
    // 9) pair-graph attention: q/k/v in ONE batched launch (z=3)
    gemm_tc<false,false,false><<<dim3(12, 24, 3), 256, GT_SMEM>>>(pair1, wqkv, nullptr, qb,
        BPn, EMBn, EMBn, EMBn, EMBn, EMBn, 0, 768L*768, 1520L*768, 1.f, 0L);
    gemm_tc<true,false,false><<<dim3(6, 6, 4), 256, GT_SMEM>>>(qb, kb, nullptr, scb,
        Pn, Pn, EMBn, EMBn, EMBn, Pn, 380L*768, 380L*768, 380L*380, SCALE_EMB, 0L);
    pair_softmax_k<<<BPn, 128>>>(scb, vis);
    gemm_tc<false,false,false><<<dim3(12, 6, 4), 256, GT_SMEM>>>(scb, vb, nullptr, atto,
        Pn, EMBn, Pn, Pn, EMBn, EMBn, 380L*380, 380L*768, 380L*768, 1.f, 0L);
    // 10) classifier head
    catfeat_k<<<BPn, 256>>>(hs_t, ts_t, pair1, atto, catf);
    gemm_tc<false,true,true><<<dim3(12, 24, 1), 256, GT_SMEM>>>(catf, Wp1, bp1, h1,
        BPn, EMBn, 2304, 2304, EMBn, EMBn, 0, 0, 0, 1.f, 0L);
    gemm_tc<false,true,false><<<dim3(2, 24, 1), 256, GT_SMEM>>>(h1, Wp2, bp2, out,
        BPn, NCLSn, EMBn, EMBn, NCLSn, NCLSn, 0, 0, 0, 1.f, 0L);
}

// round 12
// speedup vs baseline: 1.4360x; 1.4183x over previous
#include <cuda_runtime.h>
#include <cuda_fp16.h>
#include <stdint.h>
#include <math.h>

// ---------------- problem constants ----------------
#define Bn   4
#define Cn   512
#define Hn   768
#define NHn  12
#define NEn  20
#define MMn  23
#define Pn   380
#define BPn  1520
#define QSn  128
#define EMBn 768
#define NBn  12
#define BLKn 64
#define NCLSn 97
#define POSn 128

static __device__ __constant__ float kNEG = -10000.0f;
#define SCALE_EMB 0.03608439182435161f   // 1/sqrt(768)

// ---------------- scratch ----------------
#define OFF_ENT_EMB 0UL
#define OFF_ENT_ATT (OFF_ENT_EMB + 1840UL*768)
#define OFF_ENT_Q   (OFF_ENT_ATT + 960UL*512)
#define OFF_HT_ATT  (OFF_ENT_Q   + 1840UL*128)
#define OFF_RS      (OFF_HT_ATT  + 1520UL*512)
#define OFF_HTQ     (OFF_RS      + 1520UL*768)
#define OFF_HS_ATT  (OFF_HTQ     + 1520UL*128)
#define OFF_TS_ATT  (OFF_HS_ATT  + 1520UL*768)
#define OFF_CAT_H   (OFF_TS_ATT  + 1520UL*768)
#define OFF_CAT_T   (OFF_CAT_H   + 1520UL*1536)
#define OFF_HS      (OFF_CAT_T   + 1520UL*1536)
#define OFF_TS      (OFF_HS      + 1520UL*768)
#define OFF_PAIRG   (OFF_TS      + 1520UL*768)
#define OFF_CATPP   (OFF_PAIRG   + 1520UL*768)
#define OFF_PAIR1   (OFF_CATPP   + 1520UL*1024)
#define OFF_QB      (OFF_PAIR1   + 1520UL*768)
#define OFF_KB      (OFF_QB      + 1520UL*768)
#define OFF_VB      (OFF_KB      + 1520UL*768)
#define OFF_SC      (OFF_VB      + 1520UL*768)
#define OFF_ATTO    (OFF_SC      + 4UL*380*380)
#define OFF_CATF    (OFF_ATTO    + 1520UL*768)
#define OFF_H1      (OFF_CATF    + 1520UL*2304)
#define OFF_WCAT    (OFF_H1      + 1520UL*768)
#define OFF_WQKV    (OFF_WCAT    + 2UL*1536*768)
#define OFF_WB      (OFF_WQKV    + 3UL*768*768)
#define SCRATCH_TOTAL (OFF_WB    + 2UL*768)

__device__ float g_scratch[SCRATCH_TOTAL];

// ---------------- helpers ----------------
__device__ __forceinline__ uint32_t f2tf32(float x) {
    uint32_t r; asm("cvt.rna.tf32.f32 %0, %1;" : "=r"(r) : "f"(x)); return r;
}
__device__ __forceinline__ void mma_tf32(float* c, const uint32_t* a, const uint32_t* b) {
    asm volatile("mma.sync.aligned.m16n8k8.row.col.f32.tf32.tf32.f32 "
        "{%0,%1,%2,%3}, {%4,%5,%6,%7}, {%8,%9}, {%0,%1,%2,%3};"
        : "+f"(c[0]), "+f"(c[1]), "+f"(c[2]), "+f"(c[3])
        : "r"(a[0]), "r"(a[1]), "r"(a[2]), "r"(a[3]), "r"(b[0]), "r"(b[1]));
}
__device__ __forceinline__ uint32_t f2h2(float lo, float hi) {
    __half2 h = __floats2half2_rn(lo, hi);
    return *(uint32_t*)&h;
}
__device__ __forceinline__ void mma_f16(float* c, const uint32_t* a, const uint32_t* b) {
    asm volatile("mma.sync.aligned.m16n8k16.row.col.f32.f16.f16.f32 "
        "{%0,%1,%2,%3}, {%4,%5,%6,%7}, {%8,%9}, {%0,%1,%2,%3};"
        : "+f"(c[0]), "+f"(c[1]), "+f"(c[2]), "+f"(c[3])
        : "r"(a[0]), "r"(a[1]), "r"(a[2]), "r"(a[3]), "r"(b[0]), "r"(b[1]));
}
__device__ __forceinline__ void cp16(void* s, const void* g, int sz) {
    uint32_t sa = (uint32_t)__cvta_generic_to_shared(s);
    asm volatile("cp.async.cg.shared.global [%0], [%1], 16, %2;" :: "r"(sa), "l"(g), "r"(sz));
}
__device__ __forceinline__ void cp4(void* s, const void* g, int sz) {
    uint32_t sa = (uint32_t)__cvta_generic_to_shared(s);
    asm volatile("cp.async.ca.shared.global [%0], [%1], 4, %2;" :: "r"(sa), "l"(g), "r"(sz));
}
__device__ __forceinline__ void cp_commit() { asm volatile("cp.async.commit_group;"); }
template<int Ng> __device__ __forceinline__ void cp_wait() {
    asm volatile("cp.async.wait_group %0;" :: "n"(Ng));
}

// ---------------- tf32 GEMM: 64x64xBK32, 256 thr (8 warps of 16x32), 3-stage cp.async ----------------
#define GT_BM 64
#define GT_BN 64
#define GT_BK 32
#define GT_SMEM (3 * 2304 * 2 * 4)

template<bool TRANSB, bool BIAS, bool TANH>
__global__ __launch_bounds__(256, 2)
void gemm_tc(const float* __restrict__ A, const float* __restrict__ Bm,
             const float* __restrict__ bias, float* __restrict__ C,
             int M, int N, int K, int lda, int ldb, int ldc,
             long sA, long sB, long sC, float alpha, long sBias)
{
    extern __shared__ float sm[];
    float* As = sm;                     // [3][64][36]
    float* Bs = sm + 3 * 2304;          // [3][32][72] (!T) or [3][64][36] (T)
    const int tid = threadIdx.x;
    const int wid = tid >> 5, lane = tid & 31;
    const int gid = lane >> 2, tig = lane & 3;
    const int m0 = blockIdx.y * GT_BM, n0 = blockIdx.x * GT_BN;
    A  += (long)blockIdx.z * sA;
    Bm += (long)blockIdx.z * sB;
    C  += (long)blockIdx.z * sC;
    if (BIAS) bias += (long)blockIdx.z * sBias;
    const int wm0 = (wid & 3) * 16, wn0 = (wid >> 2) * 32;
    float acc[4][4] = {};

    const int ar = tid >> 2, akc = (tid & 3) * 8;
    const int bkr = tid >> 3, bnc = (tid & 7) * 8;
    const bool a_ok = (m0 + ar) < M;
    const bool b4 = (!TRANSB) && (((ldb & 3) != 0) || ((N & 3) != 0));
    const int nk = (K + GT_BK - 1) / GT_BK;

    auto issueA = [&](int kt, int st) {
        float* dst = As + st * 2304 + ar * 36 + akc;
        const float* src = A + (long)(m0 + ar) * lda + kt * GT_BK + akc;
        #pragma unroll
        for (int q = 0; q < 2; ++q) {
            int sz = (a_ok && (kt * GT_BK + akc + 4 * q) < K) ? 16 : 0;
            cp16(dst + 4 * q, src + 4 * q, sz);
        }
    };
    auto issueB = [&](int kt, int st) {
        if (!TRANSB) {
            float* dst = Bs + st * 2304 + bkr * 72 + bnc;
            const float* src = Bm + (long)(kt * GT_BK + bkr) * ldb + n0 + bnc;
            const bool kok = (kt * GT_BK + bkr) < K;
            if (!b4) {
                #pragma unroll
                for (int q = 0; q < 2; ++q) {
                    int sz = (kok && (n0 + bnc + 4 * q) < N) ? 16 : 0;
                    cp16(dst + 4 * q, src + 4 * q, sz);
                }
            } else {
                #pragma unroll
                for (int e = 0; e < 8; ++e) {
                    int sz = (kok && (n0 + bnc + e) < N) ? 4 : 0;
                    cp4(dst + e, src + e, sz);
                }
            }
        } else {
            float* dst = Bs + st * 2304 + ar * 36 + akc;
            const float* src = Bm + (long)(n0 + ar) * ldb + kt * GT_BK + akc;
            const bool nok = (n0 + ar) < N;
            #pragma unroll
            for (int q = 0; q < 2; ++q) {
                int sz = (nok && (kt * GT_BK + akc + 4 * q) < K) ? 16 : 0;
                cp16(dst + 4 * q, src + 4 * q, sz);
            }
        }
    };

    issueA(0, 0); issueB(0, 0); cp_commit();
    if (nk > 1) { issueA(1, 1); issueB(1, 1); }
    cp_commit();

    int st = 0;
    for (int kt = 0; kt < nk; ++kt) {
        cp_wait<1>();
        __syncthreads();
        const int ktn = kt + 2;
        if (ktn < nk) {
            const int stn = (st + 2 >= 3) ? st - 1 : st + 2;
            issueA(ktn, stn); issueB(ktn, stn);
        }
        cp_commit();
        const float* Ac = As + st * 2304;
        const float* Bc = Bs + st * 2304;
        #pragma unroll
        for (int kk = 0; kk < GT_BK; kk += 8) {
            uint32_t af[4], bf[4][2];
            af[0] = f2tf32(Ac[(wm0 + gid) * 36 + kk + tig]);
            af[1] = f2tf32(Ac[(wm0 + 8 + gid) * 36 + kk + tig]);
            af[2] = f2tf32(Ac[(wm0 + gid) * 36 + kk + tig + 4]);
            af[3] = f2tf32(Ac[(wm0 + 8 + gid) * 36 + kk + tig + 4]);
            #pragma unroll
            for (int nf = 0; nf < 4; ++nf) {
                const int c = wn0 + nf * 8 + gid;
                if (!TRANSB) {
                    bf[nf][0] = f2tf32(Bc[(kk + tig) * 72 + c]);
                    bf[nf][1] = f2tf32(Bc[(kk + tig + 4) * 72 + c]);
                } else {
                    bf[nf][0] = f2tf32(Bc[c * 36 + kk + tig]);
                    bf[nf][1] = f2tf32(Bc[c * 36 + kk + tig + 4]);
                }
            }
            #pragma unroll
            for (int nf = 0; nf < 4; ++nf)
                mma_tf32(acc[nf], af, bf[nf]);
        }
        st = (st + 1 >= 3) ? 0 : st + 1;
    }
    // ---- epilogue ----
    #pragma unroll
    for (int nf = 0; nf < 4; ++nf) {
        const int r = m0 + wm0 + gid;
        const int c = n0 + wn0 + nf * 8 + tig * 2;
        #pragma unroll
        for (int half = 0; half < 2; ++half) {
            const int rr = r + half * 8;
            if (rr >= M) continue;
            #pragma unroll
            for (int j = 0; j < 2; ++j) {
                const int cc = c + j;
                if (cc >= N) continue;
                float v = acc[nf][half * 2 + j] * alpha;
                if (BIAS) v += bias[cc];
                if (TANH) v = tanhf(v);
                C[(long)rr * ldc + cc] = v;
            }
        }
    }
}

// ---------------- bilinear: fp16 mma (m16n8k16), 512 thr, M-tile 128, 4-stage cp.async ----------------
// C[m,n] = sum_{nb,i,j} Hs[m,nb*64+i]*Ts[m,nb*64+j]*W[(nb*4096+i*64+j), n] + bias[n]
// W smem rows stride 76 (bank-conflict-free for the k16 fragment pattern).
#define BL_WSTRIDE 76
#define BL_WSTAGE  (64 * BL_WSTRIDE)
#define BL_SMEM    ((2*128*68 + 4*BL_WSTAGE) * 4)
__global__ __launch_bounds__(512)
void bilinear_tc(const float* __restrict__ Hs, const float* __restrict__ Ts,
                 const float* __restrict__ W, const float* __restrict__ bias,
                 float* __restrict__ C, int M)
{
    extern __shared__ float sm[];
    float* bh = sm;                      // [128][68]
    float* bt = sm + 128 * 68;           // [128][68]
    float* Ws = sm + 2 * 128 * 68;       // [4][64][76]
    const int tid = threadIdx.x;
    const int wid = tid >> 5, lane = tid & 31;
    const int gid = lane >> 2, tig = lane & 3;
    const int m0 = blockIdx.y * 128, n0 = blockIdx.x * 64;
    const int wm0 = (wid & 3) * 32, wn0 = (wid >> 2) * 16;   // 16 warps: 4m x 4n
    float acc[2][2][4] = {};
    const int lr = tid >> 2, lc = (tid & 3) * 16;            // HT loads: 128 rows
    const bool lok = (m0 + lr) < M;
    const int wr = tid >> 3, wc = (tid & 7) * 8;             // W loads: 64 rows x 64
    uint32_t btf[2][4][4];                                   // fp16 A-fragments per nb

#define LOADHT(nb_) { \
    const float* hp = Hs + (long)(m0 + lr) * 768 + (nb_) * 64 + lc; \
    const float* tp = Ts + (long)(m0 + lr) * 768 + (nb_) * 64 + lc; \
    _Pragma("unroll") for (int q_ = 0; q_ < 4; ++q_) { \
        float4 hv = lok ? *(const float4*)(hp + 4 * q_) : make_float4(0, 0, 0, 0); \
        float4 tv = lok ? *(const float4*)(tp + 4 * q_) : make_float4(0, 0, 0, 0); \
        *(float4*)&bh[lr * 68 + lc + 4 * q_] = hv; \
        *(float4*)&bt[lr * 68 + lc + 4 * q_] = tv; } }

#define ISSUEW(t_, st_) { \
    float* dst_ = Ws + (st_) * BL_WSTAGE + wr * BL_WSTRIDE + wc; \
    const float* src_ = W + ((long)(t_) * 64 + wr) * 768 + n0 + wc; \
    cp16(dst_, src_, 16); cp16(dst_ + 4, src_ + 4, 16); }

#define CACHEBT() { \
    _Pragma("unroll") for (int mf_ = 0; mf_ < 2; ++mf_) { const int r0_ = wm0 + mf_ * 16; \
        _Pragma("unroll") for (int j0_ = 0; j0_ < 4; ++j0_) { \
            const int k0_ = j0_ * 16 + tig * 2; \
            btf[mf_][j0_][0] = f2h2(bt[(r0_ + gid) * 68 + k0_],     bt[(r0_ + gid) * 68 + k0_ + 1]); \
            btf[mf_][j0_][1] = f2h2(bt[(r0_ + 8 + gid) * 68 + k0_], bt[(r0_ + 8 + gid) * 68 + k0_ + 1]); \
            btf[mf_][j0_][2] = f2h2(bt[(r0_ + gid) * 68 + k0_ + 8], bt[(r0_ + gid) * 68 + k0_ + 9]); \
            btf[mf_][j0_][3] = f2h2(bt[(r0_ + 8 + gid) * 68 + k0_ + 8], bt[(r0_ + 8 + gid) * 68 + k0_ + 9]); } } }

    LOADHT(0);
    ISSUEW(0, 0); cp_commit();
    ISSUEW(1, 1); cp_commit();
    ISSUEW(2, 2); cp_commit();
    __syncthreads();
    CACHEBT();

    for (int t = 0; t < NBn * 64; ++t) {
        const int st = t & 3;
        cp_wait<2>();
        __syncthreads();
        if (t + 3 < NBn * 64) { ISSUEW(t + 3, (t + 3) & 3); }
        cp_commit();
        const float* Wc = Ws + st * BL_WSTAGE;
        const int i = t & 63;
        float D[2][2][4] = {};
        #pragma unroll
        for (int j0 = 0; j0 < 4; ++j0) {
            const int k0 = j0 * 16 + tig * 2;
            uint32_t bfp[2][2];
            #pragma unroll
            for (int nf = 0; nf < 2; ++nf) {
                const int c = wn0 + nf * 8 + gid;
                bfp[nf][0] = f2h2(Wc[k0 * BL_WSTRIDE + c],       Wc[(k0 + 1) * BL_WSTRIDE + c]);
                bfp[nf][1] = f2h2(Wc[(k0 + 8) * BL_WSTRIDE + c], Wc[(k0 + 9) * BL_WSTRIDE + c]);
            }
            #pragma unroll
            for (int mf = 0; mf < 2; ++mf)
                #pragma unroll
                for (int nf = 0; nf < 2; ++nf)
                    mma_f16(D[mf][nf], btf[mf][j0], bfp[nf]);
        }
        #pragma unroll
        for (int mf = 0; mf < 2; ++mf) {
            const float b0 = bh[(wm0 + mf * 16 + gid) * 68 + i];
            const float b1 = bh[(wm0 + mf * 16 + 8 + gid) * 68 + i];
            #pragma unroll
            for (int nf = 0; nf < 2; ++nf) {
                acc[mf][nf][0] = fmaf(b0, D[mf][nf][0], acc[mf][nf][0]);
                acc[mf][nf][1] = fmaf(b0, D[mf][nf][1], acc[mf][nf][1]);
                acc[mf][nf][2] = fmaf(b1, D[mf][nf][2], acc[mf][nf][2]);
                acc[mf][nf][3] = fmaf(b1, D[mf][nf][3], acc[mf][nf][3]);
            }
        }
        if ((t & 63) == 63 && t + 1 < NBn * 64) {
            __syncthreads();
            LOADHT((t + 1) >> 6);
            __syncthreads();
            CACHEBT();
        }
    }
#undef LOADHT
#undef ISSUEW
#undef CACHEBT
    #pragma unroll
    for (int mf = 0; mf < 2; ++mf) {
        #pragma unroll
        for (int nf = 0; nf < 2; ++nf) {
            const int r = m0 + wm0 + mf * 16 + gid;
            const int c = n0 + wn0 + nf * 8 + tig * 2;
            if (r < M) {
                C[(long)r * 768 + c]     = acc[mf][nf][0] + bias[c];
                C[(long)r * 768 + c + 1] = acc[mf][nf][1] + bias[c + 1];
            }
            if (r + 8 < M) {
                C[(long)(r + 8) * 768 + c]     = acc[mf][nf][2] + bias[c];
                C[(long)(r + 8) * 768 + c + 1] = acc[mf][nf][3] + bias[c + 1];
            }
        }
    }
}

// ---------------- small fused kernels ----------------
__global__ void ent_emb_k(const float* __restrict__ seq, const int* __restrict__ midx,
                          const float* __restrict__ mmask, float* __restrict__ ent_emb)
{
    const int blk = blockIdx.x;
    const int b = blk / (MMn * NEn);
    const int idx = midx[blk];
    const float mask = mmask[blk];
    const float* src = seq + ((long)b * Cn + idx) * Hn;
    float* dst = ent_emb + (long)blk * Hn;
    for (int h = threadIdx.x; h < Hn; h += 256) dst[h] = mask * src[h];
}

__global__ void ent_att_k(const float* __restrict__ att, const int* __restrict__ midx,
                          const float* __restrict__ mmask, float* __restrict__ ent_att)
{
    const int blk = blockIdx.x;
    const int nh = blk % NHn;
    const int e  = (blk / NHn) % NEn;
    const int b  = blk / (NHn * NEn);
    const int c  = threadIdx.x;
    const int* mi = midx + (b * NEn + e) * MMn;
    const float* mk = mmask + (b * NEn + e) * MMn;
    float cnt = 0.f, s = 0.f;
    for (int m = 0; m < MMn; ++m) {
        const float w = mk[m];
        cnt += w;
        s += w * att[(((long)b * NHn + nh) * Cn + mi[m]) * Cn + c];
    }
    ent_att[(long)blk * Cn + c] = s / cnt;
}

__global__ void ht_att_k(const float* __restrict__ ent_att, const int* __restrict__ hts,
                         float* __restrict__ ht_att)
{
    const int bp = blockIdx.x;
    const int b = bp / Pn;
    const int hi = hts[bp * 2], ti = hts[bp * 2 + 1];
    const int c = threadIdx.x;
    const float* ha = ent_att + (long)(b * NEn + hi) * NHn * Cn;
    const float* ta = ent_att + (long)(b * NEn + ti) * NHn * Cn;
    float v = 0.f;
    #pragma unroll
    for (int nh = 0; nh < NHn; ++nh) v += ha[nh * Cn + c] * ta[nh * Cn + c];
    v *= (1.f / 12.f);
    __shared__ float red[512];
    red[c] = v; __syncthreads();
    for (int s = 256; s > 0; s >>= 1) { if (c < s) red[c] += red[c + s]; __syncthreads(); }
    ht_att[(long)bp * Cn + c] = v / (red[0] + 1e-5f);
}

__global__ void pool_attn_k(const float* __restrict__ htq, const float* __restrict__ ent_q,
                            const float* __restrict__ ent_emb, const float* __restrict__ mmask,
                            const int* __restrict__ hts, float* __restrict__ hs_att,
                            float* __restrict__ ts_att)
{
    const int bp = blockIdx.x;
    const int side = blockIdx.y;
    const int b = bp / Pn;
    const int e = hts[bp * 2 + side];
    __shared__ float qs[QSn];
    __shared__ float gs[MMn];
    const int tid = threadIdx.x;
    if (tid < QSn) qs[tid] = htq[(long)bp * QSn + tid];
    __syncthreads();
    if (tid < MMn) {
        const float* eq = ent_q + ((long)(b * NEn + e) * MMn + tid) * QSn;
        float d = 0.f;
        for (int i = 0; i < QSn; ++i) d += qs[i] * eq[i];
        const float mk = mmask[(b * NEn + e) * MMn + tid];
        gs[tid] = (mk > 0.f) ? d * SCALE_EMB : kNEG;
    }
    __syncthreads();
    float mx = -1e30f;
    for (int m = 0; m < MMn; ++m) mx = fmaxf(mx, gs[m]);
    float w[MMn]; float ssum = 0.f;
    for (int m = 0; m < MMn; ++m) { w[m] = expf(gs[m] - mx); ssum += w[m]; }
    const float inv = 1.f / ssum;
    const float* emb = ent_emb + (long)(b * NEn + e) * MMn * Hn;
    float* out = (side ? ts_att : hs_att) + (long)bp * Hn;
    for (int h = tid; h < Hn; h += 256) {
        float acc2 = 0.f;
        for (int m = 0; m < MMn; ++m) acc2 += w[m] * emb[m * Hn + h];
        out[h] = acc2 * inv;
    }
}

__global__ void cat2_k(const float* __restrict__ hs_att, const float* __restrict__ ts_att,
                       const float* __restrict__ rs, float* __restrict__ cat_h,
                       float* __restrict__ cat_t)
{
    const long r = blockIdx.x;
    for (int h = threadIdx.x; h < Hn; h += 256) {
        const float rv = rs[r * Hn + h];
        cat_h[r * 1536 + h]       = hs_att[r * Hn + h];
        cat_h[r * 1536 + 768 + h] = rv;
        cat_t[r * 1536 + h]       = ts_att[r * Hn + h];
        cat_t[r * 1536 + 768 + h] = rv;
    }
}

__global__ void catpp_k(const float* __restrict__ pairg, const float* __restrict__ pos_emb,
                        const int* __restrict__ hts, float* __restrict__ catpp)
{
    const long r = blockIdx.x;
    const int hi = hts[r * 2], ti = hts[r * 2 + 1];
    if (threadIdx.x < POSn) {
        catpp[r * 1024 + threadIdx.x]       = pos_emb[hi * POSn + threadIdx.x];
        catpp[r * 1024 + 896 + threadIdx.x] = pos_emb[ti * POSn + threadIdx.x];
    }
    for (int h = threadIdx.x; h < Hn; h += 256)
        catpp[r * 1024 + 128 + h] = pairg[r * Hn + h];
}

__global__ void pair_softmax_k(float* __restrict__ sc, const float* __restrict__ vis)
{
    const long bp = blockIdx.x;
    float* row = sc + bp * Pn;
    const float* vr = vis + bp * Pn;
    const int tid = threadIdx.x;
    __shared__ float red[128];
    float mx = -1e30f;
    for (int q = tid; q < Pn; q += 128) {
        const float v = (vr[q] > 0.f) ? row[q] : kNEG;
        mx = fmaxf(mx, v);
    }
    red[tid] = mx; __syncthreads();
    for (int s = 64; s > 0; s >>= 1) { if (tid < s) red[tid] = fmaxf(red[tid], red[tid + s]); __syncthreads(); }
    mx = red[0]; __syncthreads();
    float sum = 0.f;
    for (int q = tid; q < Pn; q += 128) {
        const float v = (vr[q] > 0.f) ? row[q] : kNEG;
        sum += expf(v - mx);
    }
    red[tid] = sum; __syncthreads();
    for (int s = 64; s > 0; s >>= 1) { if (tid < s) red[tid] += red[tid + s]; __syncthreads(); }
    const float inv = 1.f / red[0];
    for (int q = tid; q < Pn; q += 128) {
        const float v = (vr[q] > 0.f) ? row[q] : kNEG;
        row[q] = expf(v - mx) * inv;
    }
}

__global__ void catfeat_k(const float* __restrict__ hs, const float* __restrict__ ts,
                          const float* __restrict__ pair1, const float* __restrict__ atto,
                          float* __restrict__ catf)
{
    const long r = blockIdx.x;
    for (int h = threadIdx.x; h < Hn; h += 256) {
        catf[r * 2304 + h]        = hs[r * Hn + h];
        catf[r * 2304 + 768 + h]  = ts[r * Hn + h];
        catf[r * 2304 + 1536 + h] = pair1[r * Hn + h] + atto[r * Hn + h];
    }
}

// ---------------- launcher ----------------
extern "C" void kernel_launch(void* const* d_in, const int* in_sizes, int n_in,
                              void* d_out, int out_size)
{
    (void)in_sizes; (void)n_in; (void)out_size;
    const float* seq   = (const float*)d_in[0];
    const float* att   = (const float*)d_in[1];
    const int*   midx  = (const int*)  d_in[2];
    const float* mmask = (const float*)d_in[3];
    const int*   hts   = (const int*)  d_in[4];
    const float* vis   = (const float*)d_in[5];
    const float* Wcq = (const float*)d_in[6],  *bcq = (const float*)d_in[7];
    const float* Weq = (const float*)d_in[8],  *beq = (const float*)d_in[9];
    const float* Whe = (const float*)d_in[10], *bhe = (const float*)d_in[11];
    const float* Wte = (const float*)d_in[12], *bte = (const float*)d_in[13];
    const float* Wbl = (const float*)d_in[14], *bbl = (const float*)d_in[15];
    const float* Wpp = (const float*)d_in[16], *bpp = (const float*)d_in[17];
    const float* Wgq = (const float*)d_in[18];
    const float* Wgk = (const float*)d_in[19];
    const float* Wgv = (const float*)d_in[20];
    const float* Wp1 = (const float*)d_in[21], *bp1 = (const float*)d_in[22];
    const float* Wp2 = (const float*)d_in[23], *bp2 = (const float*)d_in[24];
    const float* pos = (const float*)d_in[25];
    float* out = (float*)d_out;

    float* base = nullptr;
    cudaGetSymbolAddress((void**)&base, g_scratch);
    float* ent_emb = base + OFF_ENT_EMB;
    float* ent_att = base + OFF_ENT_ATT;
    float* ent_q   = base + OFF_ENT_Q;
    float* ht_att  = base + OFF_HT_ATT;
    float* rs      = base + OFF_RS;
    float* htqb    = base + OFF_HTQ;
    float* hs_att  = base + OFF_HS_ATT;
    float* ts_att  = base + OFF_TS_ATT;
    float* cat_h   = base + OFF_CAT_H;
    float* hs_t    = base + OFF_HS;
    float* ts_t    = base + OFF_TS;
    float* pairg   = base + OFF_PAIRG;
    float* catpp   = base + OFF_CATPP;
    float* pair1   = base + OFF_PAIR1;
    float* qb      = base + OFF_QB;
    float* kb      = base + OFF_KB;
    float* vb      = base + OFF_VB;
    float* scb     = base + OFF_SC;
    float* atto    = base + OFF_ATTO;
    float* catf    = base + OFF_CATF;
    float* h1      = base + OFF_H1;
    float* wcat    = base + OFF_WCAT;
    float* wqkv    = base + OFF_WQKV;
    float* wb      = base + OFF_WB;

    cudaFuncSetAttribute(gemm_tc<false,false,false>, cudaFuncAttributeMaxDynamicSharedMemorySize, GT_SMEM);
    cudaFuncSetAttribute(gemm_tc<false,true,false>,  cudaFuncAttributeMaxDynamicSharedMemorySize, GT_SMEM);
    cudaFuncSetAttribute(gemm_tc<false,true,true>,   cudaFuncAttributeMaxDynamicSharedMemorySize, GT_SMEM);
    cudaFuncSetAttribute(gemm_tc<true,false,false>,  cudaFuncAttributeMaxDynamicSharedMemorySize, GT_SMEM);
    cudaFuncSetAttribute(bilinear_tc, cudaFuncAttributeMaxDynamicSharedMemorySize, BL_SMEM);

    // 0) pack batched weights/biases for z-batched launches
    cudaMemcpyAsync(wcat,              Whe, 1536UL*768*4, cudaMemcpyDeviceToDevice);
    cudaMemcpyAsync(wcat + 1536UL*768, Wte, 1536UL*768*4, cudaMemcpyDeviceToDevice);
    cudaMemcpyAsync(wqkv,              Wgq, 768UL*768*4,  cudaMemcpyDeviceToDevice);
    cudaMemcpyAsync(wqkv + 768UL*768,  Wgk, 768UL*768*4,  cudaMemcpyDeviceToDevice);
    cudaMemcpyAsync(wqkv + 2UL*768*768,Wgv, 768UL*768*4,  cudaMemcpyDeviceToDevice);
    cudaMemcpyAsync(wb,                bhe, 768UL*4,      cudaMemcpyDeviceToDevice);
    cudaMemcpyAsync(wb + 768,          bte, 768UL*4,      cudaMemcpyDeviceToDevice);

    // 1) entity gathers
    ent_emb_k<<<Bn * NEn * MMn, 256>>>(seq, midx, mmask, ent_emb);
    ent_att_k<<<Bn * NEn * NHn, 512>>>(att, midx, mmask, ent_att);
    // 2) pair context attention
    ht_att_k<<<BPn, 512>>>(ent_att, hts, ht_att);
    // 3) rs = ht_att @ seq (batched)
    gemm_tc<false,false,false><<<dim3(12, 6, 4), 256, GT_SMEM>>>(ht_att, seq, nullptr, rs,
        Pn, Hn, Cn, Cn, Hn, Hn, 380L*512, 512L*768, 380L*768, 1.f, 0L);
    // 4) htq, ent_q
    gemm_tc<false,true,false><<<dim3(2, 24, 1), 256, GT_SMEM>>>(rs, Wcq, bcq, htqb,
        BPn, QSn, Hn, Hn, QSn, QSn, 0, 0, 0, 1.f, 0L);
    gemm_tc<false,true,false><<<dim3(2, 29, 1), 256, GT_SMEM>>>(ent_emb, Weq, beq, ent_q,
        1840, QSn, Hn, Hn, QSn, QSn, 0, 0, 0, 1.f, 0L);
    // 5) mention-pool softmax
    pool_attn_k<<<dim3(BPn, 2), 256>>>(htqb, ent_q, ent_emb, mmask, hts, hs_att, ts_att);
    // 6) hs/ts projections — ONE z=2 batched launch (per-z bias)
    cat2_k<<<BPn, 256>>>(hs_att, ts_att, rs, cat_h, base + OFF_CAT_T);
    gemm_tc<false,true,true><<<dim3(12, 24, 2), 256, GT_SMEM>>>(cat_h, wcat, wb, hs_t,
        BPn, EMBn, 1536, 1536, EMBn, EMBn, 1520L*1536, 1536L*768, 1520L*768, 1.f, 768L);
    // 7) grouped bilinear (fp16 mma)
    bilinear_tc<<<dim3(12, 12), 512, BL_SMEM>>>(hs_t, ts_t, Wbl, bbl, pairg, BPn);
    // 8) pos concat + Wpp
    catpp_k<<<BPn, 256>>>(pairg, pos, hts, catpp);
    gemm_tc<false,true,true><<<dim3(12, 24, 1), 256, GT_SMEM>>>(catpp, Wpp, bpp, pair1,
        BPn, EMBn, 1024, 1024, EMBn, EMBn, 0, 0, 0, 1.f, 0L);
    // 9) pair-graph attention: q/k/v in ONE batched launch (z=3)
    gemm_tc<false,false,false><<<dim3(12, 24, 3), 256, GT_SMEM>>>(pair1, wqkv, nullptr, qb,
        BPn, EMBn, EMBn, EMBn, EMBn, EMBn, 0, 768L*768, 1520L*768, 1.f, 0L);
    gemm_tc<true,false,false><<<dim3(6, 6, 4), 256, GT_SMEM>>>(qb, kb, nullptr, scb,
        Pn, Pn, EMBn, EMBn, EMBn, Pn, 380L*768, 380L*768, 380L*380, SCALE_EMB, 0L);
    pair_softmax_k<<<BPn, 128>>>(scb, vis);
    gemm_tc<false,false,false><<<dim3(12, 6, 4), 256, GT_SMEM>>>(scb, vb, nullptr, atto,
        Pn, EMBn, Pn, Pn, EMBn, EMBn, 380L*380, 380L*768, 380L*768, 1.f, 0L);
    // 10) classifier head
    catfeat_k<<<BPn, 256>>>(hs_t, ts_t, pair1, atto, catf);
    gemm_tc<false,true,true><<<dim3(12, 24, 1), 256, GT_SMEM>>>(catf, Wp1, bp1, h1,
        BPn, EMBn, 2304, 2304, EMBn, EMBn, 0, 0, 0, 1.f, 0L);
    gemm_tc<false,true,false><<<dim3(2, 24, 1), 256, GT_SMEM>>>(h1, Wp2, bp2, out,
        BPn, NCLSn, EMBn, EMBn, NCLSn, NCLSn, 0, 0, 0, 1.f, 0L);
}

// round 13
// speedup vs baseline: 1.6064x; 1.1187x over previous
#include <cuda_runtime.h>
#include <cuda_fp16.h>
#include <stdint.h>
#include <math.h>

// ---------------- problem constants ----------------
#define Bn   4
#define Cn   512
#define Hn   768
#define NHn  12
#define NEn  20
#define MMn  23
#define Pn   380
#define BPn  1520
#define QSn  128
#define EMBn 768
#define NBn  12
#define BLKn 64
#define NCLSn 97
#define POSn 128

static __device__ __constant__ float kNEG = -10000.0f;
#define SCALE_EMB 0.03608439182435161f   // 1/sqrt(768)

// ---------------- scratch ----------------
#define OFF_ENT_EMB 0UL
#define OFF_ENT_ATT (OFF_ENT_EMB + 1840UL*768)
#define OFF_ENT_Q   (OFF_ENT_ATT + 960UL*512)
#define OFF_HT_ATT  (OFF_ENT_Q   + 1840UL*128)
#define OFF_RS      (OFF_HT_ATT  + 1520UL*512)
#define OFF_HTQ     (OFF_RS      + 1520UL*768)
#define OFF_HS_ATT  (OFF_HTQ     + 1520UL*128)
#define OFF_TS_ATT  (OFF_HS_ATT  + 1520UL*768)
#define OFF_CAT_H   (OFF_TS_ATT  + 1520UL*768)
#define OFF_CAT_T   (OFF_CAT_H   + 1520UL*1536)
#define OFF_HS      (OFF_CAT_T   + 1520UL*1536)
#define OFF_TS      (OFF_HS      + 1520UL*768)
#define OFF_PAIRG   (OFF_TS      + 1520UL*768)
#define OFF_CATPP   (OFF_PAIRG   + 1520UL*768)
#define OFF_PAIR1   (OFF_CATPP   + 1520UL*1024)
#define OFF_QB      (OFF_PAIR1   + 1520UL*768)
#define OFF_KB      (OFF_QB      + 1520UL*768)
#define OFF_VB      (OFF_KB      + 1520UL*768)
#define OFF_SC      (OFF_VB      + 1520UL*768)
#define OFF_ATTO    (OFF_SC      + 4UL*380*380)
#define OFF_CATF    (OFF_ATTO    + 1520UL*768)
#define OFF_H1      (OFF_CATF    + 1520UL*2304)
#define OFF_WCAT    (OFF_H1      + 1520UL*768)
#define OFF_WQKV    (OFF_WCAT    + 2UL*1536*768)
#define OFF_WB      (OFF_WQKV    + 3UL*768*768)
#define OFF_WHF     (OFF_WB      + 2UL*768)          // 768*24576 u32 (half2-packed W)
#define SCRATCH_TOTAL (OFF_WHF   + 768UL*24576)

__device__ float g_scratch[SCRATCH_TOTAL];

// ---------------- helpers ----------------
__device__ __forceinline__ uint32_t f2tf32(float x) {
    uint32_t r; asm("cvt.rna.tf32.f32 %0, %1;" : "=r"(r) : "f"(x)); return r;
}
__device__ __forceinline__ void mma_tf32(float* c, const uint32_t* a, const uint32_t* b) {
    asm volatile("mma.sync.aligned.m16n8k8.row.col.f32.tf32.tf32.f32 "
        "{%0,%1,%2,%3}, {%4,%5,%6,%7}, {%8,%9}, {%0,%1,%2,%3};"
        : "+f"(c[0]), "+f"(c[1]), "+f"(c[2]), "+f"(c[3])
        : "r"(a[0]), "r"(a[1]), "r"(a[2]), "r"(a[3]), "r"(b[0]), "r"(b[1]));
}
__device__ __forceinline__ uint32_t f2h2(float lo, float hi) {
    __half2 h = __floats2half2_rn(lo, hi);
    return *(uint32_t*)&h;
}
__device__ __forceinline__ void mma_f16(float* c, const uint32_t* a, const uint32_t* b) {
    asm volatile("mma.sync.aligned.m16n8k16.row.col.f32.f16.f16.f32 "
        "{%0,%1,%2,%3}, {%4,%5,%6,%7}, {%8,%9}, {%0,%1,%2,%3};"
        : "+f"(c[0]), "+f"(c[1]), "+f"(c[2]), "+f"(c[3])
        : "r"(a[0]), "r"(a[1]), "r"(a[2]), "r"(a[3]), "r"(b[0]), "r"(b[1]));
}
__device__ __forceinline__ void cp16(void* s, const void* g, int sz) {
    uint32_t sa = (uint32_t)__cvta_generic_to_shared(s);
    asm volatile("cp.async.cg.shared.global [%0], [%1], 16, %2;" :: "r"(sa), "l"(g), "r"(sz));
}
__device__ __forceinline__ void cp4(void* s, const void* g, int sz) {
    uint32_t sa = (uint32_t)__cvta_generic_to_shared(s);
    asm volatile("cp.async.ca.shared.global [%0], [%1], 4, %2;" :: "r"(sa), "l"(g), "r"(sz));
}
__device__ __forceinline__ void cp_commit() { asm volatile("cp.async.commit_group;"); }
template<int Ng> __device__ __forceinline__ void cp_wait() {
    asm volatile("cp.async.wait_group %0;" :: "n"(Ng));
}

// ---------------- tf32 GEMM: 64x64xBK32, 256 thr (8 warps of 16x32), 3-stage cp.async ----------------
#define GT_BM 64
#define GT_BN 64
#define GT_BK 32
#define GT_SMEM (3 * 2304 * 2 * 4)

template<bool TRANSB, bool BIAS, bool TANH>
__global__ __launch_bounds__(256, 2)
void gemm_tc(const float* __restrict__ A, const float* __restrict__ Bm,
             const float* __restrict__ bias, float* __restrict__ C,
             int M, int N, int K, int lda, int ldb, int ldc,
             long sA, long sB, long sC, float alpha, long sBias)
{
    extern __shared__ float sm[];
    float* As = sm;                     // [3][64][36]
    float* Bs = sm + 3 * 2304;          // [3][32][72] (!T) or [3][64][36] (T)
    const int tid = threadIdx.x;
    const int wid = tid >> 5, lane = tid & 31;
    const int gid = lane >> 2, tig = lane & 3;
    const int m0 = blockIdx.y * GT_BM, n0 = blockIdx.x * GT_BN;
    A  += (long)blockIdx.z * sA;
    Bm += (long)blockIdx.z * sB;
    C  += (long)blockIdx.z * sC;
    if (BIAS) bias += (long)blockIdx.z * sBias;
    const int wm0 = (wid & 3) * 16, wn0 = (wid >> 2) * 32;
    float acc[4][4] = {};

    const int ar = tid >> 2, akc = (tid & 3) * 8;
    const int bkr = tid >> 3, bnc = (tid & 7) * 8;
    const bool a_ok = (m0 + ar) < M;
    const bool b4 = (!TRANSB) && (((ldb & 3) != 0) || ((N & 3) != 0));
    const int nk = (K + GT_BK - 1) / GT_BK;

    auto issueA = [&](int kt, int st) {
        float* dst = As + st * 2304 + ar * 36 + akc;
        const float* src = A + (long)(m0 + ar) * lda + kt * GT_BK + akc;
        #pragma unroll
        for (int q = 0; q < 2; ++q) {
            int sz = (a_ok && (kt * GT_BK + akc + 4 * q) < K) ? 16 : 0;
            cp16(dst + 4 * q, src + 4 * q, sz);
        }
    };
    auto issueB = [&](int kt, int st) {
        if (!TRANSB) {
            float* dst = Bs + st * 2304 + bkr * 72 + bnc;
            const float* src = Bm + (long)(kt * GT_BK + bkr) * ldb + n0 + bnc;
            const bool kok = (kt * GT_BK + bkr) < K;
            if (!b4) {
                #pragma unroll
                for (int q = 0; q < 2; ++q) {
                    int sz = (kok && (n0 + bnc + 4 * q) < N) ? 16 : 0;
                    cp16(dst + 4 * q, src + 4 * q, sz);
                }
            } else {
                #pragma unroll
                for (int e = 0; e < 8; ++e) {
                    int sz = (kok && (n0 + bnc + e) < N) ? 4 : 0;
                    cp4(dst + e, src + e, sz);
                }
            }
        } else {
            float* dst = Bs + st * 2304 + ar * 36 + akc;
            const float* src = Bm + (long)(n0 + ar) * ldb + kt * GT_BK + akc;
            const bool nok = (n0 + ar) < N;
            #pragma unroll
            for (int q = 0; q < 2; ++q) {
                int sz = (nok && (kt * GT_BK + akc + 4 * q) < K) ? 16 : 0;
                cp16(dst + 4 * q, src + 4 * q, sz);
            }
        }
    };

    issueA(0, 0); issueB(0, 0); cp_commit();
    if (nk > 1) { issueA(1, 1); issueB(1, 1); }
    cp_commit();

    int st = 0;
    for (int kt = 0; kt < nk; ++kt) {
        cp_wait<1>();
        __syncthreads();
        const int ktn = kt + 2;
        if (ktn < nk) {
            const int stn = (st + 2 >= 3) ? st - 1 : st + 2;
            issueA(ktn, stn); issueB(ktn, stn);
        }
        cp_commit();
        const float* Ac = As + st * 2304;
        const float* Bc = Bs + st * 2304;
        #pragma unroll
        for (int kk = 0; kk < GT_BK; kk += 8) {
            uint32_t af[4], bf[4][2];
            af[0] = f2tf32(Ac[(wm0 + gid) * 36 + kk + tig]);
            af[1] = f2tf32(Ac[(wm0 + 8 + gid) * 36 + kk + tig]);
            af[2] = f2tf32(Ac[(wm0 + gid) * 36 + kk + tig + 4]);
            af[3] = f2tf32(Ac[(wm0 + 8 + gid) * 36 + kk + tig + 4]);
            #pragma unroll
            for (int nf = 0; nf < 4; ++nf) {
                const int c = wn0 + nf * 8 + gid;
                if (!TRANSB) {
                    bf[nf][0] = f2tf32(Bc[(kk + tig) * 72 + c]);
                    bf[nf][1] = f2tf32(Bc[(kk + tig + 4) * 72 + c]);
                } else {
                    bf[nf][0] = f2tf32(Bc[c * 36 + kk + tig]);
                    bf[nf][1] = f2tf32(Bc[c * 36 + kk + tig + 4]);
                }
            }
            #pragma unroll
            for (int nf = 0; nf < 4; ++nf)
                mma_tf32(acc[nf], af, bf[nf]);
        }
        st = (st + 1 >= 3) ? 0 : st + 1;
    }
    // ---- epilogue ----
    #pragma unroll
    for (int nf = 0; nf < 4; ++nf) {
        const int r = m0 + wm0 + gid;
        const int c = n0 + wn0 + nf * 8 + tig * 2;
        #pragma unroll
        for (int half = 0; half < 2; ++half) {
            const int rr = r + half * 8;
            if (rr >= M) continue;
            #pragma unroll
            for (int j = 0; j < 2; ++j) {
                const int cc = c + j;
                if (cc >= N) continue;
                float v = acc[nf][half * 2 + j] * alpha;
                if (BIAS) v += bias[cc];
                if (TANH) v = tanhf(v);
                C[(long)rr * ldc + cc] = v;
            }
        }
    }
}

// ---------------- W pre-convert: fp32 [49152][768] -> half2-packed [768][32][768] ----------------
// Whf[t*24576 + p*768 + c] = half2(W[(t*64+2p)*768 + c], W[(t*64+2p+1)*768 + c])
__global__ __launch_bounds__(256)
void conv_w_k(const float* __restrict__ W, uint32_t* __restrict__ Whf)
{
    const int t = blockIdx.x;
    const int tid = threadIdx.x;
    const float* Wt = W + (long)t * 64 * 768;
    uint32_t* Dt = Whf + (long)t * 24576;
    #pragma unroll 1
    for (int p = 0; p < 32; ++p) {
        const float* r0 = Wt + (2 * p) * 768;
        const float* r1 = Wt + (2 * p + 1) * 768;
        #pragma unroll
        for (int j = 0; j < 3; ++j) {
            const int c = tid + j * 256;
            Dt[p * 768 + c] = f2h2(r0[c], r1[c]);
        }
    }
}

// ---------------- bilinear: fp16 mma, pre-packed half2 W, 512 thr, M-tile 128 ----------------
// C[m,n] = sum_{nb,i,j} Hs[m,nb*64+i]*Ts[m,nb*64+j]*W[(nb*4096+i*64+j), n] + bias[n]
// W smem: [4 stages][32 pair-rows][72 u32] — fragment LDS conflict-free (bank = 8*tig+gid).
#define BL_WSTRIDE 72
#define BL_WSTAGE  (32 * BL_WSTRIDE)
#define BL_SMEM    ((2*128*68 + 4*BL_WSTAGE) * 4)
__global__ __launch_bounds__(512)
void bilinear_tc(const float* __restrict__ Hs, const float* __restrict__ Ts,
                 const uint32_t* __restrict__ Whf, const float* __restrict__ bias,
                 float* __restrict__ C, int M)
{
    extern __shared__ float sm[];
    float* bh = sm;                      // [128][68]
    float* bt = sm + 128 * 68;           // [128][68]
    uint32_t* Ws = (uint32_t*)(sm + 2 * 128 * 68);   // [4][32][72]
    const int tid = threadIdx.x;
    const int wid = tid >> 5, lane = tid & 31;
    const int gid = lane >> 2, tig = lane & 3;
    const int m0 = blockIdx.y * 128, n0 = blockIdx.x * 64;
    const int wm0 = (wid & 3) * 32, wn0 = (wid >> 2) * 16;   // 16 warps: 4m x 4n
    float acc[2][2][4] = {};
    const int lr = tid >> 2, lc = (tid & 3) * 16;            // HT loads: 128 rows
    const bool lok = (m0 + lr) < M;
    const int wr = tid >> 2, wq = tid & 3;                   // W loads: 32 pair-rows x 4 chunks (threads 0..127)
    uint32_t btf[2][4][4];

#define LOADHT(nb_) { \
    const float* hp = Hs + (long)(m0 + lr) * 768 + (nb_) * 64 + lc; \
    const float* tp = Ts + (long)(m0 + lr) * 768 + (nb_) * 64 + lc; \
    _Pragma("unroll") for (int q_ = 0; q_ < 4; ++q_) { \
        float4 hv = lok ? *(const float4*)(hp + 4 * q_) : make_float4(0, 0, 0, 0); \
        float4 tv = lok ? *(const float4*)(tp + 4 * q_) : make_float4(0, 0, 0, 0); \
        *(float4*)&bh[lr * 68 + lc + 4 * q_] = hv; \
        *(float4*)&bt[lr * 68 + lc + 4 * q_] = tv; } }

#define ISSUEW(t_, st_) { \
    if (tid < 128) { \
        uint32_t* dst_ = Ws + (st_) * BL_WSTAGE + wr * BL_WSTRIDE + wq * 16; \
        const uint32_t* src_ = Whf + (long)(t_) * 24576 + wr * 768 + n0 + wq * 16; \
        cp16(dst_, src_, 16); cp16(dst_ + 4, src_ + 4, 16); \
        cp16(dst_ + 8, src_ + 8, 16); cp16(dst_ + 12, src_ + 12, 16); } }

#define CACHEBT() { \
    _Pragma("unroll") for (int mf_ = 0; mf_ < 2; ++mf_) { const int r0_ = wm0 + mf_ * 16; \
        _Pragma("unroll") for (int j0_ = 0; j0_ < 4; ++j0_) { \
            const int k0_ = j0_ * 16 + tig * 2; \
            btf[mf_][j0_][0] = f2h2(bt[(r0_ + gid) * 68 + k0_],     bt[(r0_ + gid) * 68 + k0_ + 1]); \
            btf[mf_][j0_][1] = f2h2(bt[(r0_ + 8 + gid) * 68 + k0_], bt[(r0_ + 8 + gid) * 68 + k0_ + 1]); \
            btf[mf_][j0_][2] = f2h2(bt[(r0_ + gid) * 68 + k0_ + 8], bt[(r0_ + gid) * 68 + k0_ + 9]); \
            btf[mf_][j0_][3] = f2h2(bt[(r0_ + 8 + gid) * 68 + k0_ + 8], bt[(r0_ + 8 + gid) * 68 + k0_ + 9]); } } }

    LOADHT(0);
    ISSUEW(0, 0); cp_commit();
    ISSUEW(1, 1); cp_commit();
    ISSUEW(2, 2); cp_commit();
    __syncthreads();
    CACHEBT();

    for (int t = 0; t < NBn * 64; ++t) {
        const int st = t & 3;
        cp_wait<2>();
        __syncthreads();
        if (t + 3 < NBn * 64) { ISSUEW(t + 3, (t + 3) & 3); }
        cp_commit();
        const uint32_t* Wc = Ws + st * BL_WSTAGE;
        const int i = t & 63;
        float D[2][2][4] = {};
        #pragma unroll
        for (int j0 = 0; j0 < 4; ++j0) {
            uint32_t bfp[2][2];
            #pragma unroll
            for (int nf = 0; nf < 2; ++nf) {
                const int c = wn0 + nf * 8 + gid;
                bfp[nf][0] = Wc[(j0 * 8 + tig) * BL_WSTRIDE + c];
                bfp[nf][1] = Wc[(j0 * 8 + tig + 4) * BL_WSTRIDE + c];
            }
            #pragma unroll
            for (int mf = 0; mf < 2; ++mf)
                #pragma unroll
                for (int nf = 0; nf < 2; ++nf)
                    mma_f16(D[mf][nf], btf[mf][j0], bfp[nf]);
        }
        #pragma unroll
        for (int mf = 0; mf < 2; ++mf) {
            const float b0 = bh[(wm0 + mf * 16 + gid) * 68 + i];
            const float b1 = bh[(wm0 + mf * 16 + 8 + gid) * 68 + i];
            #pragma unroll
            for (int nf = 0; nf < 2; ++nf) {
                acc[mf][nf][0] = fmaf(b0, D[mf][nf][0], acc[mf][nf][0]);
                acc[mf][nf][1] = fmaf(b0, D[mf][nf][1], acc[mf][nf][1]);
                acc[mf][nf][2] = fmaf(b1, D[mf][nf][2], acc[mf][nf][2]);
                acc[mf][nf][3] = fmaf(b1, D[mf][nf][3], acc[mf][nf][3]);
            }
        }
        if ((t & 63) == 63 && t + 1 < NBn * 64) {
            __syncthreads();
            LOADHT((t + 1) >> 6);
            __syncthreads();
            CACHEBT();
        }
    }
#undef LOADHT
#undef ISSUEW
#undef CACHEBT
    #pragma unroll
    for (int mf = 0; mf < 2; ++mf) {
        #pragma unroll
        for (int nf = 0; nf < 2; ++nf) {
            const int r = m0 + wm0 + mf * 16 + gid;
            const int c = n0 + wn0 + nf * 8 + tig * 2;
            if (r < M) {
                C[(long)r * 768 + c]     = acc[mf][nf][0] + bias[c];
                C[(long)r * 768 + c + 1] = acc[mf][nf][1] + bias[c + 1];
            }
            if (r + 8 < M) {
                C[(long)(r + 8) * 768 + c]     = acc[mf][nf][2] + bias[c];
                C[(long)(r + 8) * 768 + c + 1] = acc[mf][nf][3] + bias[c + 1];
            }
        }
    }
}

// ---------------- small fused kernels ----------------
__global__ void ent_emb_k(const float* __restrict__ seq, const int* __restrict__ midx,
                          const float* __restrict__ mmask, float* __restrict__ ent_emb)
{
    const int blk = blockIdx.x;
    const int b = blk / (MMn * NEn);
    const int idx = midx[blk];
    const float mask = mmask[blk];
    const float* src = seq + ((long)b * Cn + idx) * Hn;
    float* dst = ent_emb + (long)blk * Hn;
    for (int h = threadIdx.x; h < Hn; h += 256) dst[h] = mask * src[h];
}

__global__ void ent_att_k(const float* __restrict__ att, const int* __restrict__ midx,
                          const float* __restrict__ mmask, float* __restrict__ ent_att)
{
    const int blk = blockIdx.x;
    const int nh = blk % NHn;
    const int e  = (blk / NHn) % NEn;
    const int b  = blk / (NHn * NEn);
    const int c  = threadIdx.x;
    const int* mi = midx + (b * NEn + e) * MMn;
    const float* mk = mmask + (b * NEn + e) * MMn;
    float cnt = 0.f, s = 0.f;
    for (int m = 0; m < MMn; ++m) {
        const float w = mk[m];
        cnt += w;
        s += w * att[(((long)b * NHn + nh) * Cn + mi[m]) * Cn + c];
    }
    ent_att[(long)blk * Cn + c] = s / cnt;
}

__global__ void ht_att_k(const float* __restrict__ ent_att, const int* __restrict__ hts,
                         float* __restrict__ ht_att)
{
    const int bp = blockIdx.x;
    const int b = bp / Pn;
    const int hi = hts[bp * 2], ti = hts[bp * 2 + 1];
    const int c = threadIdx.x;
    const float* ha = ent_att + (long)(b * NEn + hi) * NHn * Cn;
    const float* ta = ent_att + (long)(b * NEn + ti) * NHn * Cn;
    float v = 0.f;
    #pragma unroll
    for (int nh = 0; nh < NHn; ++nh) v += ha[nh * Cn + c] * ta[nh * Cn + c];
    v *= (1.f / 12.f);
    __shared__ float red[512];
    red[c] = v; __syncthreads();
    for (int s = 256; s > 0; s >>= 1) { if (c < s) red[c] += red[c + s]; __syncthreads(); }
    ht_att[(long)bp * Cn + c] = v / (red[0] + 1e-5f);
}

__global__ void pool_attn_k(const float* __restrict__ htq, const float* __restrict__ ent_q,
                            const float* __restrict__ ent_emb, const float* __restrict__ mmask,
                            const int* __restrict__ hts, float* __restrict__ hs_att,
                            float* __restrict__ ts_att)
{
    const int bp = blockIdx.x;
    const int side = blockIdx.y;
    const int b = bp / Pn;
    const int e = hts[bp * 2 + side];
    __shared__ float qs[QSn];
    __shared__ float gs[MMn];
    const int tid = threadIdx.x;
    if (tid < QSn) qs[tid] = htq[(long)bp * QSn + tid];
    __syncthreads();
    if (tid < MMn) {
        const float* eq = ent_q + ((long)(b * NEn + e) * MMn + tid) * QSn;
        float d = 0.f;
        for (int i = 0; i < QSn; ++i) d += qs[i] * eq[i];
        const float mk = mmask[(b * NEn + e) * MMn + tid];
        gs[tid] = (mk > 0.f) ? d * SCALE_EMB : kNEG;
    }
    __syncthreads();
    float mx = -1e30f;
    for (int m = 0; m < MMn; ++m) mx = fmaxf(mx, gs[m]);
    float w[MMn]; float ssum = 0.f;
    for (int m = 0; m < MMn; ++m) { w[m] = expf(gs[m] - mx); ssum += w[m]; }
    const float inv = 1.f / ssum;
    const float* emb = ent_emb + (long)(b * NEn + e) * MMn * Hn;
    float* out = (side ? ts_att : hs_att) + (long)bp * Hn;
    for (int h = tid; h < Hn; h += 256) {
        float acc2 = 0.f;
        for (int m = 0; m < MMn; ++m) acc2 += w[m] * emb[m * Hn + h];
        out[h] = acc2 * inv;
    }
}

__global__ void cat2_k(const float* __restrict__ hs_att, const float* __restrict__ ts_att,
                       const float* __restrict__ rs, float* __restrict__ cat_h,
                       float* __restrict__ cat_t)
{
    const long r = blockIdx.x;
    for (int h = threadIdx.x; h < Hn; h += 256) {
        const float rv = rs[r * Hn + h];
        cat_h[r * 1536 + h]       = hs_att[r * Hn + h];
        cat_h[r * 1536 + 768 + h] = rv;
        cat_t[r * 1536 + h]       = ts_att[r * Hn + h];
        cat_t[r * 1536 + 768 + h] = rv;
    }
}

__global__ void catpp_k(const float* __restrict__ pairg, const float* __restrict__ pos_emb,
                        const int* __restrict__ hts, float* __restrict__ catpp)
{
    const long r = blockIdx.x;
    const int hi = hts[r * 2], ti = hts[r * 2 + 1];
    if (threadIdx.x < POSn) {
        catpp[r * 1024 + threadIdx.x]       = pos_emb[hi * POSn + threadIdx.x];
        catpp[r * 1024 + 896 + threadIdx.x] = pos_emb[ti * POSn + threadIdx.x];
    }
    for (int h = threadIdx.x; h < Hn; h += 256)
        catpp[r * 1024 + 128 + h] = pairg[r * Hn + h];
}

__global__ void pair_softmax_k(float* __restrict__ sc, const float* __restrict__ vis)
{
    const long bp = blockIdx.x;
    float* row = sc + bp * Pn;
    const float* vr = vis + bp * Pn;
    const int tid = threadIdx.x;
    __shared__ float red[128];
    float mx = -1e30f;
    for (int q = tid; q < Pn; q += 128) {
        const float v = (vr[q] > 0.f) ? row[q] : kNEG;
        mx = fmaxf(mx, v);
    }
    red[tid] = mx; __syncthreads();
    for (int s = 64; s > 0; s >>= 1) { if (tid < s) red[tid] = fmaxf(red[tid], red[tid + s]); __syncthreads(); }
    mx = red[0]; __syncthreads();
    float sum = 0.f;
    for (int q = tid; q < Pn; q += 128) {
        const float v = (vr[q] > 0.f) ? row[q] : kNEG;
        sum += expf(v - mx);
    }
    red[tid] = sum; __syncthreads();
    for (int s = 64; s > 0; s >>= 1) { if (tid < s) red[tid] += red[tid + s]; __syncthreads(); }
    const float inv = 1.f / red[0];
    for (int q = tid; q < Pn; q += 128) {
        const float v = (vr[q] > 0.f) ? row[q] : kNEG;
        row[q] = expf(v - mx) * inv;
    }
}

__global__ void catfeat_k(const float* __restrict__ hs, const float* __restrict__ ts,
                          const float* __restrict__ pair1, const float* __restrict__ atto,
                          float* __restrict__ catf)
{
    const long r = blockIdx.x;
    for (int h = threadIdx.x; h < Hn; h += 256) {
        catf[r * 2304 + h]        = hs[r * Hn + h];
        catf[r * 2304 + 768 + h]  = ts[r * Hn + h];
        catf[r * 2304 + 1536 + h] = pair1[r * Hn + h] + atto[r * Hn + h];
    }
}

// ---------------- launcher ----------------
extern "C" void kernel_launch(void* const* d_in, const int* in_sizes, int n_in,
                              void* d_out, int out_size)
{
    (void)in_sizes; (void)n_in; (void)out_size;
    const float* seq   = (const float*)d_in[0];
    const float* att   = (const float*)d_in[1];
    const int*   midx  = (const int*)  d_in[2];
    const float* mmask = (const float*)d_in[3];
    const int*   hts   = (const int*)  d_in[4];
    const float* vis   = (const float*)d_in[5];
    const float* Wcq = (const float*)d_in[6],  *bcq = (const float*)d_in[7];
    const float* Weq = (const float*)d_in[8],  *beq = (const float*)d_in[9];
    const float* Whe = (const float*)d_in[10], *bhe = (const float*)d_in[11];
    const float* Wte = (const float*)d_in[12], *bte = (const float*)d_in[13];
    const float* Wbl = (const float*)d_in[14], *bbl = (const float*)d_in[15];
    const float* Wpp = (const float*)d_in[16], *bpp = (const float*)d_in[17];
    const float* Wgq = (const float*)d_in[18];
    const float* Wgk = (const float*)d_in[19];
    const float* Wgv = (const float*)d_in[20];
    const float* Wp1 = (const float*)d_in[21], *bp1 = (const float*)d_in[22];
    const float* Wp2 = (const float*)d_in[23], *bp2 = (const float*)d_in[24];
    const float* pos = (const float*)d_in[25];
    float* out = (float*)d_out;

    float* base = nullptr;
    cudaGetSymbolAddress((void**)&base, g_scratch);
    float* ent_emb = base + OFF_ENT_EMB;
    float* ent_att = base + OFF_ENT_ATT;
    float* ent_q   = base + OFF_ENT_Q;
    float* ht_att  = base + OFF_HT_ATT;
    float* rs      = base + OFF_RS;
    float* htqb    = base + OFF_HTQ;
    float* hs_att  = base + OFF_HS_ATT;
    float* ts_att  = base + OFF_TS_ATT;
    float* cat_h   = base + OFF_CAT_H;
    float* hs_t    = base + OFF_HS;
    float* ts_t    = base + OFF_TS;
    float* pairg   = base + OFF_PAIRG;
    float* catpp   = base + OFF_CATPP;
    float* pair1   = base + OFF_PAIR1;
    float* qb      = base + OFF_QB;
    float* kb      = base + OFF_KB;
    float* vb      = base + OFF_VB;
    float* scb     = base + OFF_SC;
    float* atto    = base + OFF_ATTO;
    float* catf    = base + OFF_CATF;
    float* h1      = base + OFF_H1;
    float* wcat    = base + OFF_WCAT;
    float* wqkv    = base + OFF_WQKV;
    float* wb      = base + OFF_WB;
    uint32_t* whf  = (uint32_t*)(base + OFF_WHF);

    cudaFuncSetAttribute(gemm_tc<false,false,false>, cudaFuncAttributeMaxDynamicSharedMemorySize, GT_SMEM);
    cudaFuncSetAttribute(gemm_tc<false,true,false>,  cudaFuncAttributeMaxDynamicSharedMemorySize, GT_SMEM);
    cudaFuncSetAttribute(gemm_tc<false,true,true>,   cudaFuncAttributeMaxDynamicSharedMemorySize, GT_SMEM);
    cudaFuncSetAttribute(gemm_tc<true,false,false>,  cudaFuncAttributeMaxDynamicSharedMemorySize, GT_SMEM);
    cudaFuncSetAttribute(bilinear_tc, cudaFuncAttributeMaxDynamicSharedMemorySize, BL_SMEM);

    // 0) pack batched weights/biases; pre-convert bilinear W to half2 layout
    cudaMemcpyAsync(wcat,              Whe, 1536UL*768*4, cudaMemcpyDeviceToDevice);
    cudaMemcpyAsync(wcat + 1536UL*768, Wte, 1536UL*768*4, cudaMemcpyDeviceToDevice);
    cudaMemcpyAsync(wqkv,              Wgq, 768UL*768*4,  cudaMemcpyDeviceToDevice);
    cudaMemcpyAsync(wqkv + 768UL*768,  Wgk, 768UL*768*4,  cudaMemcpyDeviceToDevice);
    cudaMemcpyAsync(wqkv + 2UL*768*768,Wgv, 768UL*768*4,  cudaMemcpyDeviceToDevice);
    cudaMemcpyAsync(wb,                bhe, 768UL*4,      cudaMemcpyDeviceToDevice);
    cudaMemcpyAsync(wb + 768,          bte, 768UL*4,      cudaMemcpyDeviceToDevice);
    conv_w_k<<<768, 256>>>(Wbl, whf);

    // 1) entity gathers
    ent_emb_k<<<Bn * NEn * MMn, 256>>>(seq, midx, mmask, ent_emb);
    ent_att_k<<<Bn * NEn * NHn, 512>>>(att, midx, mmask, ent_att);
    // 2) pair context attention
    ht_att_k<<<BPn, 512>>>(ent_att, hts, ht_att);
    // 3) rs = ht_att @ seq (batched)
    gemm_tc<false,false,false><<<dim3(12, 6, 4), 256, GT_SMEM>>>(ht_att, seq, nullptr, rs,
        Pn, Hn, Cn, Cn, Hn, Hn, 380L*512, 512L*768, 380L*768, 1.f, 0L);
    // 4) htq, ent_q
    gemm_tc<false,true,false><<<dim3(2, 24, 1), 256, GT_SMEM>>>(rs, Wcq, bcq, htqb,
        BPn, QSn, Hn, Hn, QSn, QSn, 0, 0, 0, 1.f, 0L);
    gemm_tc<false,true,false><<<dim3(2, 29, 1), 256, GT_SMEM>>>(ent_emb, Weq, beq, ent_q,
        1840, QSn, Hn, Hn, QSn, QSn, 0, 0, 0, 1.f, 0L);
    // 5) mention-pool softmax
    pool_attn_k<<<dim3(BPn, 2), 256>>>(htqb, ent_q, ent_emb, mmask, hts, hs_att, ts_att);
    // 6) hs/ts projections — ONE z=2 batched launch (per-z bias)
    cat2_k<<<BPn, 256>>>(hs_att, ts_att, rs, cat_h, base + OFF_CAT_T);
    gemm_tc<false,true,true><<<dim3(12, 24, 2), 256, GT_SMEM>>>(cat_h, wcat, wb, hs_t,
        BPn, EMBn, 1536, 1536, EMBn, EMBn, 1520L*1536, 1536L*768, 1520L*768, 1.f, 768L);
    // 7) grouped bilinear (fp16 mma, pre-packed W)
    bilinear_tc<<<dim3(12, 12), 512, BL_SMEM>>>(hs_t, ts_t, whf, bbl, pairg, BPn);
    // 8) pos concat + Wpp
    catpp_k<<<BPn, 256>>>(pairg, pos, hts, catpp);
    gemm_tc<false,true,true><<<dim3(12, 24, 1), 256, GT_SMEM>>>(catpp, Wpp, bpp, pair1,
        BPn, EMBn, 1024, 1024, EMBn, EMBn, 0, 0, 0, 1.f, 0L);
    // 9) pair-graph attention: q/k/v in ONE batched launch (z=3)
    gemm_tc<false,false,false><<<dim3(12, 24, 3), 256, GT_SMEM>>>(pair1, wqkv, nullptr, qb,
        BPn, EMBn, EMBn, EMBn, EMBn, EMBn, 0, 768L*768, 1520L*768, 1.f, 0L);
    gemm_tc<true,false,false><<<dim3(6, 6, 4), 256, GT_SMEM>>>(qb, kb, nullptr, scb,
        Pn, Pn, EMBn, EMBn, EMBn, Pn, 380L*768, 380L*768, 380L*380, SCALE_EMB, 0L);
    pair_softmax_k<<<BPn, 128>>>(scb, vis);
    gemm_tc<false,false,false><<<dim3(12, 6, 4), 256, GT_SMEM>>>(scb, vb, nullptr, atto,
        Pn, EMBn, Pn, Pn, EMBn, EMBn, 380L*380, 380L*768, 380L*768, 1.f, 0L);
    // 10) classifier head
    catfeat_k<<<BPn, 256>>>(hs_t, ts_t, pair1, atto, catf);
    gemm_tc<false,true,true><<<dim3(12, 24, 1), 256, GT_SMEM>>>(catf, Wp1, bp1, h1,
        BPn, EMBn, 2304, 2304, EMBn, EMBn, 0, 0, 0, 1.f, 0L);
    gemm_tc<false,true,false><<<dim3(2, 24, 1), 256, GT_SMEM>>>(h1, Wp2, bp2, out,
        BPn, NCLSn, EMBn, EMBn, NCLSn, NCLSn, 0, 0, 0, 1.f, 0L);
}